// round 1
// baseline (speedup 1.0000x reference)
#include <cuda_runtime.h>
#include <cuda_bf16.h>
#include <math.h>

// Problem constants
#define NTOK 16384
#define DDIM 1024
#define HDIM 4096
#define NEXP 8
#define DOUT 4096

// ---------------- scratch (no allocations allowed) ----------------
__device__ float g_h[(long long)NTOK * DDIM];     // 64 MB: h = x@W_in + b_in
__device__ float g_he[(long long)NTOK * HDIM];    // 256 MB: per-expert hidden (reused)
__device__ float g_moe[(long long)NTOK * DDIM];   // 64 MB: combined expert output
__device__ int   g_cnt[NEXP];
__device__ int   g_bidx[NEXP * NTOK];
__device__ float g_bw[NEXP * NTOK];

// ---------------- zero kernels ----------------
__global__ void zero_i_kernel(int* p, int n) {
    int i = blockIdx.x * blockDim.x + threadIdx.x;
    if (i < n) p[i] = 0;
}

__global__ void zero_f4_kernel(float* p, long long n4) {
    long long i = blockIdx.x * (long long)blockDim.x + threadIdx.x;
    long long stride = (long long)gridDim.x * blockDim.x;
    float4 z = make_float4(0.f, 0.f, 0.f, 0.f);
    for (; i < n4; i += stride) reinterpret_cast<float4*>(p)[i] = z;
}

// ---------------- SGEMM: C[M,N] = op(A[M,K] @ B[K,N] + bias) ----------------
// gatherIdx: if non-null, A row m is A[gatherIdx[m]]
// scatterIdx/scatterW: if non-null, C[scatterIdx[m]] += scatterW[m] * (acc + bias)
// cntPtr: if non-null, M = *cntPtr (device-side count; excess tiles exit)
__global__ void __launch_bounds__(256, 2)
sgemm_kernel(const float* __restrict__ A, const float* __restrict__ B,
             float* __restrict__ C, const float* __restrict__ bias,
             const int* __restrict__ gatherIdx,
             const int* __restrict__ scatterIdx,
             const float* __restrict__ scatterW,
             const int* __restrict__ cntPtr,
             int M, int N, int K, int doRelu)
{
    __shared__ float As[8][128];
    __shared__ float Bs[8][128];

    if (cntPtr) M = __ldg(cntPtr);
    if ((int)(blockIdx.y * 128) >= M) return;

    const int tid = threadIdx.x;
    const int row0 = blockIdx.y * 128;
    const int col0 = blockIdx.x * 128;

    // A tile load mapping: 128 rows x 8 cols, one float4 per thread
    const int aRow = tid >> 1;
    const int aCol = (tid & 1) << 2;
    // B tile load mapping: 8 rows x 128 cols, one float4 per thread
    const int bRow = tid >> 5;
    const int bCol = (tid & 31) << 2;

    const int am = row0 + aRow;
    const bool aValid = am < M;
    long long aBase = 0;
    if (aValid) {
        int g = gatherIdx ? gatherIdx[am] : am;
        aBase = (long long)g * K;
    }

    const int tx = tid & 15;
    const int ty = tid >> 4;

    float acc[8][8];
#pragma unroll
    for (int i = 0; i < 8; i++)
#pragma unroll
        for (int j = 0; j < 8; j++) acc[i][j] = 0.f;

    const float* Bp = B + (long long)bRow * N + col0 + bCol;

    for (int k0 = 0; k0 < K; k0 += 8) {
        float4 a4 = make_float4(0.f, 0.f, 0.f, 0.f);
        if (aValid)
            a4 = *reinterpret_cast<const float4*>(A + aBase + k0 + aCol);
        float4 b4 = *reinterpret_cast<const float4*>(Bp + (long long)k0 * N);

        As[aCol + 0][aRow] = a4.x;
        As[aCol + 1][aRow] = a4.y;
        As[aCol + 2][aRow] = a4.z;
        As[aCol + 3][aRow] = a4.w;
        *reinterpret_cast<float4*>(&Bs[bRow][bCol]) = b4;
        __syncthreads();

#pragma unroll
        for (int kk = 0; kk < 8; kk++) {
            float rm[8], rn[8];
#pragma unroll
            for (int i = 0; i < 8; i++) rm[i] = As[kk][ty * 8 + i];
#pragma unroll
            for (int j = 0; j < 8; j++) rn[j] = Bs[kk][tx * 8 + j];
#pragma unroll
            for (int i = 0; i < 8; i++)
#pragma unroll
                for (int j = 0; j < 8; j++)
                    acc[i][j] = fmaf(rm[i], rn[j], acc[i][j]);
        }
        __syncthreads();
    }

    // ---------------- epilogue ----------------
    if (scatterIdx) {
#pragma unroll
        for (int i = 0; i < 8; i++) {
            int m = row0 + ty * 8 + i;
            if (m < M) {
                int gm = scatterIdx[m];
                float w = scatterW[m];
                float* Crow = C + (long long)gm * N + col0 + tx * 8;
#pragma unroll
                for (int j = 0; j < 8; j++) {
                    float v = acc[i][j];
                    if (bias) v += bias[col0 + tx * 8 + j];
                    Crow[j] += w * v;   // collision-free within kernel; experts serialized
                }
            }
        }
    } else {
#pragma unroll
        for (int i = 0; i < 8; i++) {
            int m = row0 + ty * 8 + i;
            if (m < M) {
                float* Crow = C + (long long)m * N + col0 + tx * 8;
#pragma unroll
                for (int j = 0; j < 8; j++) {
                    float v = acc[i][j];
                    if (bias) v += bias[col0 + tx * 8 + j];
                    if (doRelu) v = fmaxf(v, 0.f);
                    Crow[j] = v;
                }
            }
        }
    }
}

// ---------------- gating: logits, top-2, renorm weights, bucket tokens ----------------
__global__ void __launch_bounds__(256)
gate_kernel(const float* __restrict__ h, const float* __restrict__ Wg,
            int* __restrict__ cnt, int* __restrict__ bidx, float* __restrict__ bw)
{
    __shared__ float sWg[DDIM * NEXP];  // 32 KB
    const int tid = threadIdx.x;
    for (int i = tid; i < DDIM * NEXP; i += 256) sWg[i] = Wg[i];
    __syncthreads();

    const int warp = tid >> 5;
    const int lane = tid & 31;
    const int token = blockIdx.x * 8 + warp;
    if (token >= NTOK) return;

    float accv[NEXP];
#pragma unroll
    for (int e = 0; e < NEXP; e++) accv[e] = 0.f;
    const float* hrow = h + (long long)token * DDIM;
    for (int d = lane; d < DDIM; d += 32) {
        float hv = hrow[d];
#pragma unroll
        for (int e = 0; e < NEXP; e++)
            accv[e] = fmaf(hv, sWg[d * NEXP + e], accv[e]);
    }
#pragma unroll
    for (int e = 0; e < NEXP; e++) {
#pragma unroll
        for (int off = 16; off > 0; off >>= 1)
            accv[e] += __shfl_xor_sync(0xffffffffu, accv[e], off);
    }
    if (lane == 0) {
        int i1 = 0; float l1 = accv[0];
#pragma unroll
        for (int e = 1; e < NEXP; e++)
            if (accv[e] > l1) { l1 = accv[e]; i1 = e; }
        int i2 = -1; float l2 = -3.0e38f;
#pragma unroll
        for (int e = 0; e < NEXP; e++)
            if (e != i1 && accv[e] > l2) { l2 = accv[e]; i2 = e; }
        // renormalized top-2 softmax weights: e^{l}/(e^{l1}+e^{l2})
        float p2 = expf(l2 - l1);
        float w1 = 1.f / (1.f + p2);
        float w2 = p2 * w1;
        int p = atomicAdd(&cnt[i1], 1);
        bidx[i1 * NTOK + p] = token; bw[i1 * NTOK + p] = w1;
        p = atomicAdd(&cnt[i2], 1);
        bidx[i2 * NTOK + p] = token; bw[i2 * NTOK + p] = w2;
    }
}

// ---------------- launch ----------------
extern "C" void kernel_launch(void* const* d_in, const int* in_sizes, int n_in,
                              void* d_out, int out_size)
{
    const float* x      = (const float*)d_in[0];
    const float* W_in   = (const float*)d_in[1];
    const float* b_in   = (const float*)d_in[2];
    const float* W_gate = (const float*)d_in[3];
    const float* W1     = (const float*)d_in[4];
    const float* b1     = (const float*)d_in[5];
    const float* W2     = (const float*)d_in[6];
    const float* b2     = (const float*)d_in[7];
    const float* W_head = (const float*)d_in[8];
    float* out = (float*)d_out;

    float *h_p, *he_p, *moe_p, *bw_p;
    int *cnt_p, *bidx_p;
    cudaGetSymbolAddress((void**)&h_p,   g_h);
    cudaGetSymbolAddress((void**)&he_p,  g_he);
    cudaGetSymbolAddress((void**)&moe_p, g_moe);
    cudaGetSymbolAddress((void**)&cnt_p, g_cnt);
    cudaGetSymbolAddress((void**)&bidx_p,g_bidx);
    cudaGetSymbolAddress((void**)&bw_p,  g_bw);

    dim3 blk(256);

    zero_i_kernel<<<1, 32>>>(cnt_p, NEXP);
    zero_f4_kernel<<<1024, 256>>>(moe_p, (long long)NTOK * DDIM / 4);

    // h = x @ W_in + b_in            [16384,1024]
    sgemm_kernel<<<dim3(DDIM / 128, NTOK / 128), blk>>>(
        x, W_in, h_p, b_in, nullptr, nullptr, nullptr, nullptr,
        NTOK, DDIM, DDIM, 0);

    // gating + routing
    gate_kernel<<<NTOK / 8, 256>>>(h_p, W_gate, cnt_p, bidx_p, bw_p);

    // expert FFNs (sequential per expert => no data atomics needed)
    for (int e = 0; e < NEXP; e++) {
        // he = relu(h[bucket] @ W1[e] + b1[e])   [cnt_e, 4096]
        sgemm_kernel<<<dim3(HDIM / 128, NTOK / 128), blk>>>(
            h_p, W1 + (long long)e * DDIM * HDIM, he_p, b1 + (long long)e * HDIM,
            bidx_p + e * NTOK, nullptr, nullptr, cnt_p + e,
            NTOK, HDIM, DDIM, 1);
        // moe[bucket] += w * (he @ W2[e] + b2[e])   [cnt_e, 1024] scattered
        sgemm_kernel<<<dim3(DDIM / 128, NTOK / 128), blk>>>(
            he_p, W2 + (long long)e * HDIM * DDIM, moe_p, b2 + (long long)e * DDIM,
            nullptr, bidx_p + e * NTOK, bw_p + e * NTOK, cnt_p + e,
            NTOK, DDIM, HDIM, 0);
    }

    // out = moe @ W_head             [16384,4096]
    sgemm_kernel<<<dim3(DOUT / 128, NTOK / 128), blk>>>(
        moe_p, W_head, out, nullptr, nullptr, nullptr, nullptr, nullptr,
        NTOK, DOUT, DDIM, 0);
}

// round 3
// speedup vs baseline: 2.0462x; 2.0462x over previous
#include <cuda_runtime.h>
#include <cuda_bf16.h>
#include <cstdint>
#include <math.h>

// Problem constants
#define NTOK 16384
#define DDIM 1024
#define HDIM 4096
#define NEXP 8
#define DOUT 4096

// ---------------- scratch (no allocations allowed) ----------------
__device__ float g_h[(long long)NTOK * DDIM];     // 64 MB
__device__ float g_he[(long long)NTOK * HDIM];    // 256 MB
__device__ float g_moe[(long long)NTOK * DDIM];   // 64 MB
__device__ int   g_cnt[NEXP];
__device__ int   g_bidx[NEXP * NTOK];
__device__ float g_bw[NEXP * NTOK];

// ---------------- helpers ----------------
static __device__ __forceinline__ uint32_t smem_u32(const void* p) {
    uint32_t a;
    asm("{ .reg .u64 t; cvta.to.shared.u64 t, %1; cvt.u32.u64 %0, t; }"
        : "=r"(a) : "l"(p));
    return a;
}

static __device__ __forceinline__ void cp_async16(uint32_t dst, const void* src, int srcBytes) {
    asm volatile("cp.async.cg.shared.global [%0], [%1], %2, %3;"
                 :: "r"(dst), "l"(src), "n"(16), "r"(srcBytes) : "memory");
}
#define CP_COMMIT() asm volatile("cp.async.commit_group;" ::: "memory")
#define CP_WAIT(n)  asm volatile("cp.async.wait_group %0;" :: "n"(n) : "memory")

static __device__ __forceinline__ void ldsm_x4(uint32_t (&r)[4], uint32_t addr) {
    asm volatile("ldmatrix.sync.aligned.m8n8.x4.shared.b16 {%0,%1,%2,%3}, [%4];"
                 : "=r"(r[0]), "=r"(r[1]), "=r"(r[2]), "=r"(r[3]) : "r"(addr));
}
static __device__ __forceinline__ void ldsm_x4_t(uint32_t (&r)[4], uint32_t addr) {
    asm volatile("ldmatrix.sync.aligned.m8n8.x4.trans.shared.b16 {%0,%1,%2,%3}, [%4];"
                 : "=r"(r[0]), "=r"(r[1]), "=r"(r[2]), "=r"(r[3]) : "r"(addr));
}

static __device__ __forceinline__ void mma16816(float (&d)[4],
    uint32_t a0, uint32_t a1, uint32_t a2, uint32_t a3, uint32_t b0, uint32_t b1)
{
    asm volatile("mma.sync.aligned.m16n8k16.row.col.f32.bf16.bf16.f32 "
                 "{%0,%1,%2,%3}, {%4,%5,%6,%7}, {%8,%9}, {%0,%1,%2,%3};"
                 : "+f"(d[0]), "+f"(d[1]), "+f"(d[2]), "+f"(d[3])
                 : "r"(a0), "r"(a1), "r"(a2), "r"(a3), "r"(b0), "r"(b1));
}

// split fp32 pair -> hi bf16x2 + lo bf16x2
static __device__ __forceinline__ void split2(float a, float b, uint32_t& h, uint32_t& l) {
    __nv_bfloat162 hb = __float22bfloat162_rn(make_float2(a, b));
    float ra = a - __bfloat162float(hb.x);
    float rb = b - __bfloat162float(hb.y);
    __nv_bfloat162 lb = __float22bfloat162_rn(make_float2(ra, rb));
    h = *reinterpret_cast<uint32_t*>(&hb);
    l = *reinterpret_cast<uint32_t*>(&lb);
}

// ---------------- smem layout (dynamic, bytes) ----------------
// stageA[2]: fp32 [128][32]   -> 2 * 16384
// stageB[2]: fp32 [32][128]   -> 2 * 16384
// buf[2]: {Ah 8K, Al 8K, Bh 8K, Bl 8K} bf16 swizzled
#define STAGE_A_OFF 0
#define STAGE_B_OFF 32768
#define BUF_OFF     65536
#define BUF_STRIDE  32768
#define SMEM_TOTAL  131072

// ---------------- zero kernels ----------------
__global__ void zero_i_kernel(int* p, int n) {
    int i = blockIdx.x * blockDim.x + threadIdx.x;
    if (i < n) p[i] = 0;
}
__global__ void zero_f4_kernel(float* p, long long n4) {
    long long i = blockIdx.x * (long long)blockDim.x + threadIdx.x;
    long long stride = (long long)gridDim.x * blockDim.x;
    float4 z = make_float4(0.f, 0.f, 0.f, 0.f);
    for (; i < n4; i += stride) reinterpret_cast<float4*>(p)[i] = z;
}

// ---------------- split-bf16 tensor-core GEMM (mma.sync) ----------------
// C[M,N] = op(A[M,K] @ B[K,N] + bias); 3-term bf16 split for fp32 accuracy.
__global__ void __launch_bounds__(256, 1)
tc_gemm_kernel(const float* __restrict__ A, const float* __restrict__ B,
               float* __restrict__ C, const float* __restrict__ bias,
               const int* __restrict__ gatherIdx,
               const int* __restrict__ scatterIdx,
               const float* __restrict__ scatterW,
               const int* __restrict__ cntPtr,
               int M, int N, int K, int doRelu)
{
    extern __shared__ char smem[];

    if (cntPtr) M = __ldg(cntPtr);
    const int row0 = blockIdx.y * 128;
    if (row0 >= M) return;
    const int col0 = blockIdx.x * 128;

    const int tid  = threadIdx.x;
    const int lane = tid & 31;
    const int wid  = tid >> 5;
    const int wm   = wid >> 2;     // 0..1  (m offset wm*64)
    const int wn   = wid & 3;      // 0..3  (n offset wn*32)

    const uint32_t smem_base = smem_u32(smem);

    // ---- A gather pointers: 4 rows per thread (cp.async producers) ----
    const int kuA = tid & 7;               // 16B unit within row (x4 floats)
    const float* aptr[4];
    int avalid[4];
#pragma unroll
    for (int i = 0; i < 4; i++) {
        int r = (tid >> 3) + 32 * i;       // 0..127
        int m = row0 + r;
        avalid[i] = (m < M) ? 16 : 0;
        int g = (m < M) ? (gatherIdx ? gatherIdx[m] : m) : 0;
        aptr[i] = A + (long long)g * K + kuA * 4;
    }
    const int kB0 = tid >> 5;              // B stage: k row group
    const int nuB = tid & 31;              // 16B unit in n

    const int nchunk = K >> 5;             // K / 32

    // ---- ldmatrix lane addressing (constant per lane) ----
    const int rowA  = wm * 64 + (lane & 7) + ((lane >> 3) & 1) * 8;
    const int kbA   = (lane >> 4) & 1;
    const int swzA  = rowA & 3;
    const int kBld  = (lane & 7) + ((lane >> 3) & 1) * 8;   // 0..15 within kstep
    const int nbB   = (lane >> 4) & 1;
    const int kswzB = kBld & 7;

    float acc[4][4][4];
#pragma unroll
    for (int mi = 0; mi < 4; mi++)
#pragma unroll
        for (int nj = 0; nj < 4; nj++)
#pragma unroll
            for (int q = 0; q < 4; q++) acc[mi][nj][q] = 0.f;

    // ---- producer lambda-ish macros ----
#define PREFETCH(c) do {                                                        \
        int _b = (c) & 1;                                                       \
        int _k0 = (c) << 5;                                                     \
        uint32_t _sa = smem_base + STAGE_A_OFF + _b * 16384;                    \
        uint32_t _sb = smem_base + STAGE_B_OFF + _b * 16384;                    \
        _Pragma("unroll")                                                       \
        for (int _i = 0; _i < 4; _i++) {                                        \
            int _r = (tid >> 3) + 32 * _i;                                      \
            cp_async16(_sa + _r * 128 + kuA * 16, aptr[_i] + _k0, avalid[_i]);  \
        }                                                                       \
        _Pragma("unroll")                                                       \
        for (int _i = 0; _i < 4; _i++) {                                        \
            int _k = kB0 + 8 * _i;                                              \
            cp_async16(_sb + _k * 512 + nuB * 16,                               \
                       B + (long long)(_k0 + _k) * N + col0 + nuB * 4, 16);     \
        }                                                                       \
        CP_COMMIT();                                                            \
    } while (0)

#define CONVERT(c) do {                                                         \
        int _b = (c) & 1;                                                       \
        const float* _sa = reinterpret_cast<const float*>(smem + STAGE_A_OFF + _b * 16384); \
        const float* _sb = reinterpret_cast<const float*>(smem + STAGE_B_OFF + _b * 16384); \
        char* _bufAh = smem + BUF_OFF + _b * BUF_STRIDE;                        \
        char* _bufAl = _bufAh + 8192;                                           \
        char* _bufBh = _bufAh + 16384;                                          \
        char* _bufBl = _bufAh + 24576;                                          \
        _Pragma("unroll")                                                       \
        for (int _i = 0; _i < 2; _i++) {                                        \
            int _row = (tid >> 2) + 64 * _i;                                    \
            int _kg = tid & 3;                                                  \
            float4 _f0 = *reinterpret_cast<const float4*>(_sa + _row * 32 + _kg * 8);      \
            float4 _f1 = *reinterpret_cast<const float4*>(_sa + _row * 32 + _kg * 8 + 4);  \
            uint4 _h, _l;                                                       \
            split2(_f0.x, _f0.y, _h.x, _l.x);                                   \
            split2(_f0.z, _f0.w, _h.y, _l.y);                                   \
            split2(_f1.x, _f1.y, _h.z, _l.z);                                   \
            split2(_f1.z, _f1.w, _h.w, _l.w);                                   \
            uint32_t _off = _row * 64 + ((_kg ^ (_row & 3)) << 4);              \
            *reinterpret_cast<uint4*>(_bufAh + _off) = _h;                      \
            *reinterpret_cast<uint4*>(_bufAl + _off) = _l;                      \
        }                                                                       \
        _Pragma("unroll")                                                       \
        for (int _i = 0; _i < 2; _i++) {                                        \
            int _k = (tid >> 4) + 16 * _i;                                      \
            int _ng = tid & 15;                                                 \
            float4 _f0 = *reinterpret_cast<const float4*>(_sb + _k * 128 + _ng * 8);       \
            float4 _f1 = *reinterpret_cast<const float4*>(_sb + _k * 128 + _ng * 8 + 4);   \
            uint4 _h, _l;                                                       \
            split2(_f0.x, _f0.y, _h.x, _l.x);                                   \
            split2(_f0.z, _f0.w, _h.y, _l.y);                                   \
            split2(_f1.x, _f1.y, _h.z, _l.z);                                   \
            split2(_f1.z, _f1.w, _h.w, _l.w);                                   \
            uint32_t _off = _k * 256 + ((_ng ^ (_k & 7)) << 4);                 \
            *reinterpret_cast<uint4*>(_bufBh + _off) = _h;                      \
            *reinterpret_cast<uint4*>(_bufBl + _off) = _l;                      \
        }                                                                       \
    } while (0)

    // ---- prologue ----
    PREFETCH(0);
    if (nchunk > 1) PREFETCH(1);
    CP_WAIT(1);
    __syncthreads();
    CONVERT(0);
    __syncthreads();

    // ---- main loop ----
    for (int c = 0; c < nchunk; c++) {
        if (c + 2 < nchunk) { PREFETCH(c + 2); }
        if (c + 1 < nchunk) {
            if (c + 2 < nchunk) { CP_WAIT(1); } else { CP_WAIT(0); }
            CONVERT(c + 1);
        }

        // compute chunk c
        {
            const int b = c & 1;
            const uint32_t bufAh = smem_base + BUF_OFF + b * BUF_STRIDE;
            const uint32_t bufAl = bufAh + 8192;
            const uint32_t bufBh = bufAh + 16384;
            const uint32_t bufBl = bufAh + 24576;

#pragma unroll
            for (int ks = 0; ks < 2; ks++) {
                uint32_t ah[4][4], al[4][4];
#pragma unroll
                for (int mi = 0; mi < 4; mi++) {
                    uint32_t aoff = (uint32_t)((rowA + mi * 16) * 64 +
                                    (((ks * 2 + kbA) ^ swzA) << 4));
                    ldsm_x4(ah[mi], bufAh + aoff);
                    ldsm_x4(al[mi], bufAl + aoff);
                }
                uint32_t bh[2][4], bl[2][4];
#pragma unroll
                for (int j = 0; j < 2; j++) {
                    int nchk = wn * 4 + j * 2 + nbB;
                    uint32_t boff = (uint32_t)((kBld + ks * 16) * 256 +
                                    ((nchk ^ kswzB) << 4));
                    ldsm_x4_t(bh[j], bufBh + boff);
                    ldsm_x4_t(bl[j], bufBl + boff);
                }
#pragma unroll
                for (int mi = 0; mi < 4; mi++) {
#pragma unroll
                    for (int nj = 0; nj < 4; nj++) {
                        int j = nj >> 1, p = (nj & 1) * 2;
                        uint32_t b0h = bh[j][p], b1h = bh[j][p + 1];
                        uint32_t b0l = bl[j][p], b1l = bl[j][p + 1];
                        mma16816(acc[mi][nj], ah[mi][0], ah[mi][1], ah[mi][2], ah[mi][3], b0h, b1h);
                        mma16816(acc[mi][nj], ah[mi][0], ah[mi][1], ah[mi][2], ah[mi][3], b0l, b1l);
                        mma16816(acc[mi][nj], al[mi][0], al[mi][1], al[mi][2], al[mi][3], b0h, b1h);
                    }
                }
            }
        }
        __syncthreads();
    }

    // ---------------- epilogue ----------------
    const int colBase = col0 + wn * 32 + (lane & 3) * 2;
#pragma unroll
    for (int mi = 0; mi < 4; mi++) {
        int r0 = row0 + wm * 64 + mi * 16 + (lane >> 2);
        int r1 = r0 + 8;
        if (scatterIdx) {
            int g0 = 0, g1 = 0; float w0 = 0.f, w1 = 0.f;
            bool v0 = r0 < M, v1 = r1 < M;
            if (v0) { g0 = scatterIdx[r0]; w0 = scatterW[r0]; }
            if (v1) { g1 = scatterIdx[r1]; w1 = scatterW[r1]; }
#pragma unroll
            for (int nj = 0; nj < 4; nj++) {
                int col = colBase + nj * 8;
                float b0 = bias ? bias[col] : 0.f;
                float b1 = bias ? bias[col + 1] : 0.f;
                if (v0) {
                    float* p = C + (long long)g0 * N + col;
                    p[0] += w0 * (acc[mi][nj][0] + b0);
                    p[1] += w0 * (acc[mi][nj][1] + b1);
                }
                if (v1) {
                    float* p = C + (long long)g1 * N + col;
                    p[0] += w1 * (acc[mi][nj][2] + b0);
                    p[1] += w1 * (acc[mi][nj][3] + b1);
                }
            }
        } else {
#pragma unroll
            for (int nj = 0; nj < 4; nj++) {
                int col = colBase + nj * 8;
                float b0 = bias ? bias[col] : 0.f;
                float b1 = bias ? bias[col + 1] : 0.f;
                float v00 = acc[mi][nj][0] + b0;
                float v01 = acc[mi][nj][1] + b1;
                float v10 = acc[mi][nj][2] + b0;
                float v11 = acc[mi][nj][3] + b1;
                if (doRelu) {
                    v00 = fmaxf(v00, 0.f); v01 = fmaxf(v01, 0.f);
                    v10 = fmaxf(v10, 0.f); v11 = fmaxf(v11, 0.f);
                }
                if (r0 < M) { float* p = C + (long long)r0 * N + col; p[0] = v00; p[1] = v01; }
                if (r1 < M) { float* p = C + (long long)r1 * N + col; p[0] = v10; p[1] = v11; }
            }
        }
    }
#undef PREFETCH
#undef CONVERT
}

// ---------------- gating ----------------
__global__ void __launch_bounds__(256)
gate_kernel(const float* __restrict__ h, const float* __restrict__ Wg,
            int* __restrict__ cnt, int* __restrict__ bidx, float* __restrict__ bw)
{
    __shared__ float sWg[DDIM * NEXP];
    const int tid = threadIdx.x;
    for (int i = tid; i < DDIM * NEXP; i += 256) sWg[i] = Wg[i];
    __syncthreads();

    const int warp = tid >> 5;
    const int lane = tid & 31;
    const int token = blockIdx.x * 8 + warp;
    if (token >= NTOK) return;

    float accv[NEXP];
#pragma unroll
    for (int e = 0; e < NEXP; e++) accv[e] = 0.f;
    const float* hrow = h + (long long)token * DDIM;
    for (int d = lane; d < DDIM; d += 32) {
        float hv = hrow[d];
#pragma unroll
        for (int e = 0; e < NEXP; e++)
            accv[e] = fmaf(hv, sWg[d * NEXP + e], accv[e]);
    }
#pragma unroll
    for (int e = 0; e < NEXP; e++) {
#pragma unroll
        for (int off = 16; off > 0; off >>= 1)
            accv[e] += __shfl_xor_sync(0xffffffffu, accv[e], off);
    }
    if (lane == 0) {
        int i1 = 0; float l1 = accv[0];
#pragma unroll
        for (int e = 1; e < NEXP; e++)
            if (accv[e] > l1) { l1 = accv[e]; i1 = e; }
        int i2 = -1; float l2 = -3.0e38f;
#pragma unroll
        for (int e = 0; e < NEXP; e++)
            if (e != i1 && accv[e] > l2) { l2 = accv[e]; i2 = e; }
        float p2 = expf(l2 - l1);
        float w1 = 1.f / (1.f + p2);
        float w2 = p2 * w1;
        int p = atomicAdd(&cnt[i1], 1);
        bidx[i1 * NTOK + p] = token; bw[i1 * NTOK + p] = w1;
        p = atomicAdd(&cnt[i2], 1);
        bidx[i2 * NTOK + p] = token; bw[i2 * NTOK + p] = w2;
    }
}

// ---------------- launch ----------------
extern "C" void kernel_launch(void* const* d_in, const int* in_sizes, int n_in,
                              void* d_out, int out_size)
{
    const float* x      = (const float*)d_in[0];
    const float* W_in   = (const float*)d_in[1];
    const float* b_in   = (const float*)d_in[2];
    const float* W_gate = (const float*)d_in[3];
    const float* W1     = (const float*)d_in[4];
    const float* b1     = (const float*)d_in[5];
    const float* W2     = (const float*)d_in[6];
    const float* b2     = (const float*)d_in[7];
    const float* W_head = (const float*)d_in[8];
    float* out = (float*)d_out;

    float *h_p, *he_p, *moe_p, *bw_p;
    int *cnt_p, *bidx_p;
    cudaGetSymbolAddress((void**)&h_p,    g_h);
    cudaGetSymbolAddress((void**)&he_p,   g_he);
    cudaGetSymbolAddress((void**)&moe_p,  g_moe);
    cudaGetSymbolAddress((void**)&cnt_p,  g_cnt);
    cudaGetSymbolAddress((void**)&bidx_p, g_bidx);
    cudaGetSymbolAddress((void**)&bw_p,   g_bw);

    cudaFuncSetAttribute(tc_gemm_kernel,
                         cudaFuncAttributeMaxDynamicSharedMemorySize, SMEM_TOTAL);

    dim3 blk(256);

    zero_i_kernel<<<1, 32>>>(cnt_p, NEXP);
    zero_f4_kernel<<<1024, 256>>>(moe_p, (long long)NTOK * DDIM / 4);

    // h = x @ W_in + b_in   [16384,1024]
    tc_gemm_kernel<<<dim3(DDIM / 128, NTOK / 128), blk, SMEM_TOTAL>>>(
        x, W_in, h_p, b_in, nullptr, nullptr, nullptr, nullptr,
        NTOK, DDIM, DDIM, 0);

    gate_kernel<<<NTOK / 8, 256>>>(h_p, W_gate, cnt_p, bidx_p, bw_p);

    for (int e = 0; e < NEXP; e++) {
        tc_gemm_kernel<<<dim3(HDIM / 128, NTOK / 128), blk, SMEM_TOTAL>>>(
            h_p, W1 + (long long)e * DDIM * HDIM, he_p, b1 + (long long)e * HDIM,
            bidx_p + e * NTOK, nullptr, nullptr, cnt_p + e,
            NTOK, HDIM, DDIM, 1);
        tc_gemm_kernel<<<dim3(DDIM / 128, NTOK / 128), blk, SMEM_TOTAL>>>(
            he_p, W2 + (long long)e * HDIM * DDIM, moe_p, b2 + (long long)e * DDIM,
            nullptr, bidx_p + e * NTOK, bw_p + e * NTOK, cnt_p + e,
            NTOK, DDIM, HDIM, 0);
    }

    // out = moe @ W_head   [16384,4096]
    tc_gemm_kernel<<<dim3(DOUT / 128, NTOK / 128), blk, SMEM_TOTAL>>>(
        moe_p, W_head, out, nullptr, nullptr, nullptr, nullptr, nullptr,
        NTOK, DOUT, DDIM, 0);
}

// round 4
// speedup vs baseline: 2.3694x; 1.1579x over previous
#include <cuda_runtime.h>
#include <cuda_bf16.h>
#include <cstdint>
#include <math.h>

// Problem constants
#define NTOK 16384
#define DDIM 1024
#define HDIM 4096
#define NEXP 8
#define DOUT 4096

// ---------------- scratch (no allocations allowed) ----------------
__device__ float g_h[(size_t)NTOK * DDIM];      // h fp32 (for gate)
__device__ float g_moe[(size_t)NTOK * DDIM];    // combined expert out fp32
__device__ int   g_cnt[NEXP];
__device__ int   g_bidx[NEXP * NTOK];
__device__ float g_bw[NEXP * NTOK];

// split-bf16 planes (hi / lo)
__device__ __nv_bfloat16 g_xh[(size_t)NTOK * DDIM],  g_xl[(size_t)NTOK * DDIM];
__device__ __nv_bfloat16 g_hh[(size_t)NTOK * DDIM],  g_hl[(size_t)NTOK * DDIM];
__device__ __nv_bfloat16 g_heh[(size_t)NTOK * HDIM], g_hel[(size_t)NTOK * HDIM];
__device__ __nv_bfloat16 g_mh[(size_t)NTOK * DDIM],  g_ml[(size_t)NTOK * DDIM];
__device__ __nv_bfloat16 g_wih[(size_t)DDIM * DDIM], g_wil[(size_t)DDIM * DDIM];
__device__ __nv_bfloat16 g_w1h[(size_t)NEXP * DDIM * HDIM], g_w1l[(size_t)NEXP * DDIM * HDIM];
__device__ __nv_bfloat16 g_w2h[(size_t)NEXP * HDIM * DDIM], g_w2l[(size_t)NEXP * HDIM * DDIM];
__device__ __nv_bfloat16 g_whh[(size_t)DDIM * DOUT], g_whl[(size_t)DDIM * DOUT];

// ---------------- helpers ----------------
static __device__ __forceinline__ uint32_t smem_u32(const void* p) {
    uint32_t a;
    asm("{ .reg .u64 t; cvta.to.shared.u64 t, %1; cvt.u32.u64 %0, t; }"
        : "=r"(a) : "l"(p));
    return a;
}
static __device__ __forceinline__ void cp_async16(uint32_t dst, const void* src, int srcBytes) {
    asm volatile("cp.async.cg.shared.global [%0], [%1], %2, %3;"
                 :: "r"(dst), "l"(src), "n"(16), "r"(srcBytes) : "memory");
}
#define CP_COMMIT() asm volatile("cp.async.commit_group;" ::: "memory")
#define CP_WAIT(n)  asm volatile("cp.async.wait_group %0;" :: "n"(n) : "memory")

static __device__ __forceinline__ void ldsm_x4(uint32_t (&r)[4], uint32_t addr) {
    asm volatile("ldmatrix.sync.aligned.m8n8.x4.shared.b16 {%0,%1,%2,%3}, [%4];"
                 : "=r"(r[0]), "=r"(r[1]), "=r"(r[2]), "=r"(r[3]) : "r"(addr));
}
static __device__ __forceinline__ void ldsm_x4_t(uint32_t (&r)[4], uint32_t addr) {
    asm volatile("ldmatrix.sync.aligned.m8n8.x4.trans.shared.b16 {%0,%1,%2,%3}, [%4];"
                 : "=r"(r[0]), "=r"(r[1]), "=r"(r[2]), "=r"(r[3]) : "r"(addr));
}
static __device__ __forceinline__ void mma16816(float (&d)[4],
    uint32_t a0, uint32_t a1, uint32_t a2, uint32_t a3, uint32_t b0, uint32_t b1)
{
    asm volatile("mma.sync.aligned.m16n8k16.row.col.f32.bf16.bf16.f32 "
                 "{%0,%1,%2,%3}, {%4,%5,%6,%7}, {%8,%9}, {%0,%1,%2,%3};"
                 : "+f"(d[0]), "+f"(d[1]), "+f"(d[2]), "+f"(d[3])
                 : "r"(a0), "r"(a1), "r"(a2), "r"(a3), "r"(b0), "r"(b1));
}
static __device__ __forceinline__ void split2(float a, float b, uint32_t& h, uint32_t& l) {
    __nv_bfloat162 hb = __float22bfloat162_rn(make_float2(a, b));
    float ra = a - __bfloat162float(hb.x);
    float rb = b - __bfloat162float(hb.y);
    __nv_bfloat162 lb = __float22bfloat162_rn(make_float2(ra, rb));
    h = *reinterpret_cast<uint32_t*>(&hb);
    l = *reinterpret_cast<uint32_t*>(&lb);
}

// ---------------- smem layout ----------------
// per buffer: Ah 8K | Al 8K | Bh 8K | Bl 8K = 32 KB; 3 buffers = 96 KB
#define CHUNK_K   32
#define PLANE_SZ  8192
#define BUF_BYTES 32768
#define NBUF      3
#define SMEM_TOTAL (NBUF * BUF_BYTES)

// ---------------- small kernels ----------------
__global__ void zero_i_kernel(int* p, int n) {
    int i = blockIdx.x * blockDim.x + threadIdx.x;
    if (i < n) p[i] = 0;
}
__global__ void zero_f4_kernel(float* p, long long n4) {
    long long i = blockIdx.x * (long long)blockDim.x + threadIdx.x;
    long long stride = (long long)gridDim.x * blockDim.x;
    float4 z = make_float4(0.f, 0.f, 0.f, 0.f);
    for (; i < n4; i += stride) reinterpret_cast<float4*>(p)[i] = z;
}
// fp32 -> split bf16 planes (vectorized, grid-stride)
__global__ void split_kernel(const float* __restrict__ src,
                             __nv_bfloat16* __restrict__ dh,
                             __nv_bfloat16* __restrict__ dl, long long n4)
{
    long long i = blockIdx.x * (long long)blockDim.x + threadIdx.x;
    long long stride = (long long)gridDim.x * blockDim.x;
    for (; i < n4; i += stride) {
        float4 v = reinterpret_cast<const float4*>(src)[i];
        uint32_t h0, l0, h1, l1;
        split2(v.x, v.y, h0, l0);
        split2(v.z, v.w, h1, l1);
        reinterpret_cast<uint2*>(dh)[i] = make_uint2(h0, h1);
        reinterpret_cast<uint2*>(dl)[i] = make_uint2(l0, l1);
    }
}

// ---------------- split-bf16 tensor-core GEMM (pre-split inputs) ----------------
// acc = A @ B  (A[M,K] hi/lo planes, B[K,N] hi/lo planes), 3-term split.
// Outputs: Cf fp32 (optional), Oh/Ol split bf16 (optional). scatter => Cf += w*(v).
__global__ void __launch_bounds__(256, 1)
tc_gemm2(const __nv_bfloat16* __restrict__ Ah_g, const __nv_bfloat16* __restrict__ Al_g,
         const __nv_bfloat16* __restrict__ Bh_g, const __nv_bfloat16* __restrict__ Bl_g,
         float* __restrict__ Cf,
         __nv_bfloat16* __restrict__ Oh, __nv_bfloat16* __restrict__ Ol,
         const float* __restrict__ bias,
         const int* __restrict__ gatherIdx,
         const int* __restrict__ scatterIdx, const float* __restrict__ scatterW,
         const int* __restrict__ cntPtr,
         int M, int N, int K, int doRelu)
{
    extern __shared__ char smem[];

    if (cntPtr) M = __ldg(cntPtr);
    const int row0 = blockIdx.y * 128;
    if (row0 >= M) return;
    const int col0 = blockIdx.x * 128;

    const int tid  = threadIdx.x;
    const int lane = tid & 31;
    const int wid  = tid >> 5;
    const int wm   = wid >> 2;
    const int wn   = wid & 3;

    const uint32_t smem_base = smem_u32(smem);

    // producer mapping
    const int rA  = tid >> 1;          // A row 0..127
    const int uA0 = (tid & 1) << 1;    // A 16B-unit base (of 4)
    const int kB  = tid >> 3;          // B k row 0..31
    const int uB0 = (tid & 7) << 1;    // B 16B-unit base (of 16)

    const int mA = row0 + rA;
    const int aOk = (mA < M) ? 16 : 0;
    const int gA = (mA < M) ? (gatherIdx ? gatherIdx[mA] : mA) : 0;
    const __nv_bfloat16* aSrcH = Ah_g + (long long)gA * K;
    const __nv_bfloat16* aSrcL = Al_g + (long long)gA * K;

    const int nchunk = K / CHUNK_K;

#define PREFETCH(c) do {                                                         \
        int _b = (c) % NBUF;                                                     \
        int _k0 = (c) * CHUNK_K;                                                 \
        uint32_t _base = smem_base + _b * BUF_BYTES;                             \
        _Pragma("unroll")                                                        \
        for (int _p = 0; _p < 2; _p++) {                                         \
            int _u = uA0 + _p;                                                   \
            uint32_t _d = _base + rA * 64 + ((_u ^ (rA & 3)) << 4);              \
            cp_async16(_d,            aSrcH + _k0 + _u * 8, aOk);                \
            cp_async16(_d + PLANE_SZ, aSrcL + _k0 + _u * 8, aOk);                \
        }                                                                        \
        _Pragma("unroll")                                                        \
        for (int _p = 0; _p < 2; _p++) {                                         \
            int _u = uB0 + _p;                                                   \
            uint32_t _d = _base + 2 * PLANE_SZ + kB * 256 + ((_u ^ (kB & 7)) << 4); \
            long long _go = (long long)(_k0 + kB) * N + col0 + _u * 8;           \
            cp_async16(_d,            Bh_g + _go, 16);                           \
            cp_async16(_d + PLANE_SZ, Bl_g + _go, 16);                           \
        }                                                                        \
        CP_COMMIT();                                                             \
    } while (0)

    // ldmatrix lane addressing
    const int rowA  = wm * 64 + (lane & 7) + ((lane >> 3) & 1) * 8;
    const int kbA   = (lane >> 4) & 1;
    const int swzA  = rowA & 3;
    const int kBld  = (lane & 7) + ((lane >> 3) & 1) * 8;
    const int nbB   = (lane >> 4) & 1;
    const int kswzB = kBld & 7;

    float acc[4][4][4];
#pragma unroll
    for (int mi = 0; mi < 4; mi++)
#pragma unroll
        for (int nj = 0; nj < 4; nj++)
#pragma unroll
            for (int q = 0; q < 4; q++) acc[mi][nj][q] = 0.f;

    PREFETCH(0);
    if (nchunk > 1) PREFETCH(1);

    for (int c = 0; c < nchunk; c++) {
        if (c + 1 < nchunk) { CP_WAIT(1); } else { CP_WAIT(0); }
        __syncthreads();
        if (c + 2 < nchunk) PREFETCH(c + 2);

        const int b = c % NBUF;
        const uint32_t bufAh = smem_base + b * BUF_BYTES;
        const uint32_t bufAl = bufAh + PLANE_SZ;
        const uint32_t bufBh = bufAh + 2 * PLANE_SZ;
        const uint32_t bufBl = bufAh + 3 * PLANE_SZ;

#pragma unroll
        for (int ks = 0; ks < 2; ks++) {
            uint32_t ah[4][4], al[4][4];
#pragma unroll
            for (int mi = 0; mi < 4; mi++) {
                uint32_t aoff = (uint32_t)((rowA + mi * 16) * 64 +
                                (((ks * 2 + kbA) ^ swzA) << 4));
                ldsm_x4(ah[mi], bufAh + aoff);
                ldsm_x4(al[mi], bufAl + aoff);
            }
            uint32_t bh[2][4], bl[2][4];
#pragma unroll
            for (int j = 0; j < 2; j++) {
                int nchk = wn * 4 + j * 2 + nbB;
                uint32_t boff = (uint32_t)((kBld + ks * 16) * 256 +
                                ((nchk ^ kswzB) << 4));
                ldsm_x4_t(bh[j], bufBh + boff);
                ldsm_x4_t(bl[j], bufBl + boff);
            }
#pragma unroll
            for (int mi = 0; mi < 4; mi++) {
#pragma unroll
                for (int nj = 0; nj < 4; nj++) {
                    int j = nj >> 1, p = (nj & 1) * 2;
                    uint32_t b0h = bh[j][p], b1h = bh[j][p + 1];
                    uint32_t b0l = bl[j][p], b1l = bl[j][p + 1];
                    mma16816(acc[mi][nj], ah[mi][0], ah[mi][1], ah[mi][2], ah[mi][3], b0h, b1h);
                    mma16816(acc[mi][nj], ah[mi][0], ah[mi][1], ah[mi][2], ah[mi][3], b0l, b1l);
                    mma16816(acc[mi][nj], al[mi][0], al[mi][1], al[mi][2], al[mi][3], b0h, b1h);
                }
            }
        }
        __syncthreads();
    }

    // ---------------- epilogue ----------------
    const int colBase = col0 + wn * 32 + (lane & 3) * 2;
#pragma unroll
    for (int mi = 0; mi < 4; mi++) {
        int r0 = row0 + wm * 64 + mi * 16 + (lane >> 2);
        int r1 = r0 + 8;
        if (scatterIdx) {
            int g0 = 0, g1 = 0; float w0 = 0.f, w1 = 0.f;
            bool v0 = r0 < M, v1 = r1 < M;
            if (v0) { g0 = scatterIdx[r0]; w0 = scatterW[r0]; }
            if (v1) { g1 = scatterIdx[r1]; w1 = scatterW[r1]; }
#pragma unroll
            for (int nj = 0; nj < 4; nj++) {
                int col = colBase + nj * 8;
                float b0 = bias ? bias[col] : 0.f;
                float b1 = bias ? bias[col + 1] : 0.f;
                if (v0) {
                    float* p = Cf + (long long)g0 * N + col;
                    p[0] += w0 * (acc[mi][nj][0] + b0);
                    p[1] += w0 * (acc[mi][nj][1] + b1);
                }
                if (v1) {
                    float* p = Cf + (long long)g1 * N + col;
                    p[0] += w1 * (acc[mi][nj][2] + b0);
                    p[1] += w1 * (acc[mi][nj][3] + b1);
                }
            }
        } else {
#pragma unroll
            for (int nj = 0; nj < 4; nj++) {
                int col = colBase + nj * 8;
                float b0 = bias ? bias[col] : 0.f;
                float b1 = bias ? bias[col + 1] : 0.f;
                float v00 = acc[mi][nj][0] + b0;
                float v01 = acc[mi][nj][1] + b1;
                float v10 = acc[mi][nj][2] + b0;
                float v11 = acc[mi][nj][3] + b1;
                if (doRelu) {
                    v00 = fmaxf(v00, 0.f); v01 = fmaxf(v01, 0.f);
                    v10 = fmaxf(v10, 0.f); v11 = fmaxf(v11, 0.f);
                }
                if (r0 < M) {
                    long long o = (long long)r0 * N + col;
                    if (Cf) { Cf[o] = v00; Cf[o + 1] = v01; }
                    if (Oh) {
                        uint32_t hp, lp; split2(v00, v01, hp, lp);
                        *reinterpret_cast<uint32_t*>(Oh + o) = hp;
                        *reinterpret_cast<uint32_t*>(Ol + o) = lp;
                    }
                }
                if (r1 < M) {
                    long long o = (long long)r1 * N + col;
                    if (Cf) { Cf[o] = v10; Cf[o + 1] = v11; }
                    if (Oh) {
                        uint32_t hp, lp; split2(v10, v11, hp, lp);
                        *reinterpret_cast<uint32_t*>(Oh + o) = hp;
                        *reinterpret_cast<uint32_t*>(Ol + o) = lp;
                    }
                }
            }
        }
    }
#undef PREFETCH
}

// ---------------- gating ----------------
__global__ void __launch_bounds__(256)
gate_kernel(const float* __restrict__ h, const float* __restrict__ Wg,
            int* __restrict__ cnt, int* __restrict__ bidx, float* __restrict__ bw)
{
    __shared__ float sWg[DDIM * NEXP];
    const int tid = threadIdx.x;
    for (int i = tid; i < DDIM * NEXP; i += 256) sWg[i] = Wg[i];
    __syncthreads();

    const int warp = tid >> 5;
    const int lane = tid & 31;
    const int token = blockIdx.x * 8 + warp;
    if (token >= NTOK) return;

    float accv[NEXP];
#pragma unroll
    for (int e = 0; e < NEXP; e++) accv[e] = 0.f;
    const float* hrow = h + (long long)token * DDIM;
    for (int d = lane; d < DDIM; d += 32) {
        float hv = hrow[d];
#pragma unroll
        for (int e = 0; e < NEXP; e++)
            accv[e] = fmaf(hv, sWg[d * NEXP + e], accv[e]);
    }
#pragma unroll
    for (int e = 0; e < NEXP; e++) {
#pragma unroll
        for (int off = 16; off > 0; off >>= 1)
            accv[e] += __shfl_xor_sync(0xffffffffu, accv[e], off);
    }
    if (lane == 0) {
        int i1 = 0; float l1 = accv[0];
#pragma unroll
        for (int e = 1; e < NEXP; e++)
            if (accv[e] > l1) { l1 = accv[e]; i1 = e; }
        int i2 = -1; float l2 = -3.0e38f;
#pragma unroll
        for (int e = 0; e < NEXP; e++)
            if (e != i1 && accv[e] > l2) { l2 = accv[e]; i2 = e; }
        float p2 = expf(l2 - l1);
        float w1 = 1.f / (1.f + p2);
        float w2 = p2 * w1;
        int p = atomicAdd(&cnt[i1], 1);
        bidx[i1 * NTOK + p] = token; bw[i1 * NTOK + p] = w1;
        p = atomicAdd(&cnt[i2], 1);
        bidx[i2 * NTOK + p] = token; bw[i2 * NTOK + p] = w2;
    }
}

// ---------------- launch ----------------
extern "C" void kernel_launch(void* const* d_in, const int* in_sizes, int n_in,
                              void* d_out, int out_size)
{
    const float* x      = (const float*)d_in[0];
    const float* W_in   = (const float*)d_in[1];
    const float* b_in   = (const float*)d_in[2];
    const float* W_gate = (const float*)d_in[3];
    const float* W1     = (const float*)d_in[4];
    const float* b1     = (const float*)d_in[5];
    const float* W2     = (const float*)d_in[6];
    const float* b2     = (const float*)d_in[7];
    const float* W_head = (const float*)d_in[8];
    float* out = (float*)d_out;

    float *h_p, *moe_p, *bw_p;
    int *cnt_p, *bidx_p;
    __nv_bfloat16 *xh, *xl, *hh, *hl, *heh, *hel, *mh, *ml;
    __nv_bfloat16 *wih, *wil, *w1h, *w1l, *w2h, *w2l, *whh, *whl;
    cudaGetSymbolAddress((void**)&h_p,   g_h);
    cudaGetSymbolAddress((void**)&moe_p, g_moe);
    cudaGetSymbolAddress((void**)&cnt_p, g_cnt);
    cudaGetSymbolAddress((void**)&bidx_p,g_bidx);
    cudaGetSymbolAddress((void**)&bw_p,  g_bw);
    cudaGetSymbolAddress((void**)&xh,  g_xh);  cudaGetSymbolAddress((void**)&xl,  g_xl);
    cudaGetSymbolAddress((void**)&hh,  g_hh);  cudaGetSymbolAddress((void**)&hl,  g_hl);
    cudaGetSymbolAddress((void**)&heh, g_heh); cudaGetSymbolAddress((void**)&hel, g_hel);
    cudaGetSymbolAddress((void**)&mh,  g_mh);  cudaGetSymbolAddress((void**)&ml,  g_ml);
    cudaGetSymbolAddress((void**)&wih, g_wih); cudaGetSymbolAddress((void**)&wil, g_wil);
    cudaGetSymbolAddress((void**)&w1h, g_w1h); cudaGetSymbolAddress((void**)&w1l, g_w1l);
    cudaGetSymbolAddress((void**)&w2h, g_w2h); cudaGetSymbolAddress((void**)&w2l, g_w2l);
    cudaGetSymbolAddress((void**)&whh, g_whh); cudaGetSymbolAddress((void**)&whl, g_whl);

    cudaFuncSetAttribute(tc_gemm2,
                         cudaFuncAttributeMaxDynamicSharedMemorySize, SMEM_TOTAL);

    dim3 blk(256);

    zero_i_kernel<<<1, 32>>>(cnt_p, NEXP);
    zero_f4_kernel<<<1024, 256>>>(moe_p, (long long)NTOK * DDIM / 4);

    // pre-split inputs and weights (memory-bound, once per launch)
    split_kernel<<<2048, 256>>>(x,      xh,  xl,  (long long)NTOK * DDIM / 4);
    split_kernel<<<512,  256>>>(W_in,   wih, wil, (long long)DDIM * DDIM / 4);
    split_kernel<<<4096, 256>>>(W1,     w1h, w1l, (long long)NEXP * DDIM * HDIM / 4);
    split_kernel<<<4096, 256>>>(W2,     w2h, w2l, (long long)NEXP * HDIM * DDIM / 4);
    split_kernel<<<1024, 256>>>(W_head, whh, whl, (long long)DDIM * DOUT / 4);

    // h = x @ W_in + b_in   -> fp32 (gate) + split planes
    tc_gemm2<<<dim3(DDIM / 128, NTOK / 128), blk, SMEM_TOTAL>>>(
        xh, xl, wih, wil, h_p, hh, hl, b_in,
        nullptr, nullptr, nullptr, nullptr, NTOK, DDIM, DDIM, 0);

    gate_kernel<<<NTOK / 8, 256>>>(h_p, W_gate, cnt_p, bidx_p, bw_p);

    for (int e = 0; e < NEXP; e++) {
        // he = relu(h[bucket] @ W1[e] + b1[e]) -> split planes only
        tc_gemm2<<<dim3(HDIM / 128, NTOK / 128), blk, SMEM_TOTAL>>>(
            hh, hl, w1h + (size_t)e * DDIM * HDIM, w1l + (size_t)e * DDIM * HDIM,
            nullptr, heh, hel, b1 + (size_t)e * HDIM,
            bidx_p + e * NTOK, nullptr, nullptr, cnt_p + e,
            NTOK, HDIM, DDIM, 1);
        // moe[bucket] += w * (he @ W2[e] + b2[e])
        tc_gemm2<<<dim3(DDIM / 128, NTOK / 128), blk, SMEM_TOTAL>>>(
            heh, hel, w2h + (size_t)e * HDIM * DDIM, w2l + (size_t)e * HDIM * DDIM,
            moe_p, nullptr, nullptr, b2 + (size_t)e * DDIM,
            nullptr, bidx_p + e * NTOK, bw_p + e * NTOK, cnt_p + e,
            NTOK, DDIM, HDIM, 0);
    }

    // moe -> split planes, then head
    split_kernel<<<2048, 256>>>(moe_p, mh, ml, (long long)NTOK * DDIM / 4);
    tc_gemm2<<<dim3(DOUT / 128, NTOK / 128), blk, SMEM_TOTAL>>>(
        mh, ml, whh, whl, out, nullptr, nullptr, nullptr,
        nullptr, nullptr, nullptr, nullptr, NTOK, DOUT, DDIM, 0);
}

// round 5
// speedup vs baseline: 2.7600x; 1.1649x over previous
#include <cuda_runtime.h>
#include <cuda_bf16.h>
#include <cstdint>
#include <math.h>

// Problem constants
#define NTOK 16384
#define DDIM 1024
#define HDIM 4096
#define NEXP 8
#define DOUT 4096

// ---------------- scratch (no allocations allowed) ----------------
__device__ float g_h[(size_t)NTOK * DDIM];      // h fp32 (for gate)
__device__ float g_moe[(size_t)NTOK * DDIM];    // combined expert out fp32
__device__ int   g_cnt[NEXP];
__device__ int   g_bidx[NEXP * NTOK];
__device__ float g_bw[NEXP * NTOK];

// split-bf16 planes (hi / lo)
__device__ __nv_bfloat16 g_xh[(size_t)NTOK * DDIM],  g_xl[(size_t)NTOK * DDIM];
__device__ __nv_bfloat16 g_hh[(size_t)NTOK * DDIM],  g_hl[(size_t)NTOK * DDIM];
__device__ __nv_bfloat16 g_heh[(size_t)NTOK * HDIM], g_hel[(size_t)NTOK * HDIM];
__device__ __nv_bfloat16 g_mh[(size_t)NTOK * DDIM],  g_ml[(size_t)NTOK * DDIM];
__device__ __nv_bfloat16 g_wih[(size_t)DDIM * DDIM], g_wil[(size_t)DDIM * DDIM];
__device__ __nv_bfloat16 g_w1h[(size_t)NEXP * DDIM * HDIM], g_w1l[(size_t)NEXP * DDIM * HDIM];
__device__ __nv_bfloat16 g_w2h[(size_t)NEXP * HDIM * DDIM], g_w2l[(size_t)NEXP * HDIM * DDIM];
__device__ __nv_bfloat16 g_whh[(size_t)DDIM * DOUT], g_whl[(size_t)DDIM * DOUT];

// ---------------- helpers ----------------
static __device__ __forceinline__ uint32_t smem_u32(const void* p) {
    uint32_t a;
    asm("{ .reg .u64 t; cvta.to.shared.u64 t, %1; cvt.u32.u64 %0, t; }"
        : "=r"(a) : "l"(p));
    return a;
}
static __device__ __forceinline__ void cp_async16(uint32_t dst, const void* src, int srcBytes) {
    asm volatile("cp.async.cg.shared.global [%0], [%1], %2, %3;"
                 :: "r"(dst), "l"(src), "n"(16), "r"(srcBytes) : "memory");
}
#define CP_COMMIT() asm volatile("cp.async.commit_group;" ::: "memory")
#define CP_WAIT(n)  asm volatile("cp.async.wait_group %0;" :: "n"(n) : "memory")

static __device__ __forceinline__ void ldsm_x4(uint32_t (&r)[4], uint32_t addr) {
    asm volatile("ldmatrix.sync.aligned.m8n8.x4.shared.b16 {%0,%1,%2,%3}, [%4];"
                 : "=r"(r[0]), "=r"(r[1]), "=r"(r[2]), "=r"(r[3]) : "r"(addr));
}
static __device__ __forceinline__ void ldsm_x4_t(uint32_t (&r)[4], uint32_t addr) {
    asm volatile("ldmatrix.sync.aligned.m8n8.x4.trans.shared.b16 {%0,%1,%2,%3}, [%4];"
                 : "=r"(r[0]), "=r"(r[1]), "=r"(r[2]), "=r"(r[3]) : "r"(addr));
}
static __device__ __forceinline__ void mma16816(float (&d)[4],
    uint32_t a0, uint32_t a1, uint32_t a2, uint32_t a3, uint32_t b0, uint32_t b1)
{
    asm volatile("mma.sync.aligned.m16n8k16.row.col.f32.bf16.bf16.f32 "
                 "{%0,%1,%2,%3}, {%4,%5,%6,%7}, {%8,%9}, {%0,%1,%2,%3};"
                 : "+f"(d[0]), "+f"(d[1]), "+f"(d[2]), "+f"(d[3])
                 : "r"(a0), "r"(a1), "r"(a2), "r"(a3), "r"(b0), "r"(b1));
}
static __device__ __forceinline__ void split2(float a, float b, uint32_t& h, uint32_t& l) {
    __nv_bfloat162 hb = __float22bfloat162_rn(make_float2(a, b));
    float ra = a - __bfloat162float(hb.x);
    float rb = b - __bfloat162float(hb.y);
    __nv_bfloat162 lb = __float22bfloat162_rn(make_float2(ra, rb));
    h = *reinterpret_cast<uint32_t*>(&hb);
    l = *reinterpret_cast<uint32_t*>(&lb);
}

// ---------------- smem layout ----------------
// per buffer: Ah 16K | Al 16K | Bh 8K | Bl 8K = 48 KB; 3 buffers = 144 KB
#define CHUNK_K    32
#define A_PLANE    16384
#define B_PLANE    8192
#define B_BASE     (2 * A_PLANE)
#define BUF_BYTES  (2 * A_PLANE + 2 * B_PLANE)
#define NBUF       3
#define SMEM_TOTAL (NBUF * BUF_BYTES)

// ---------------- small kernels ----------------
__global__ void zero_i_kernel(int* p, int n) {
    int i = blockIdx.x * blockDim.x + threadIdx.x;
    if (i < n) p[i] = 0;
}
__global__ void zero_f4_kernel(float* p, long long n4) {
    long long i = blockIdx.x * (long long)blockDim.x + threadIdx.x;
    long long stride = (long long)gridDim.x * blockDim.x;
    float4 z = make_float4(0.f, 0.f, 0.f, 0.f);
    for (; i < n4; i += stride) reinterpret_cast<float4*>(p)[i] = z;
}
__global__ void split_kernel(const float* __restrict__ src,
                             __nv_bfloat16* __restrict__ dh,
                             __nv_bfloat16* __restrict__ dl, long long n4)
{
    long long i = blockIdx.x * (long long)blockDim.x + threadIdx.x;
    long long stride = (long long)gridDim.x * blockDim.x;
    for (; i < n4; i += stride) {
        float4 v = reinterpret_cast<const float4*>(src)[i];
        uint32_t h0, l0, h1, l1;
        split2(v.x, v.y, h0, l0);
        split2(v.z, v.w, h1, l1);
        reinterpret_cast<uint2*>(dh)[i] = make_uint2(h0, h1);
        reinterpret_cast<uint2*>(dl)[i] = make_uint2(l0, l1);
    }
}

// ---------------- split-bf16 tensor-core GEMM, 256x128 tile, 512 threads ----------------
__global__ void __launch_bounds__(512, 1)
tc_gemm2(const __nv_bfloat16* __restrict__ Ah_g, const __nv_bfloat16* __restrict__ Al_g,
         const __nv_bfloat16* __restrict__ Bh_g, const __nv_bfloat16* __restrict__ Bl_g,
         float* __restrict__ Cf,
         __nv_bfloat16* __restrict__ Oh, __nv_bfloat16* __restrict__ Ol,
         const float* __restrict__ bias,
         const int* __restrict__ gatherIdx,
         const int* __restrict__ scatterIdx, const float* __restrict__ scatterW,
         const int* __restrict__ cntPtr,
         int M, int N, int K, int doRelu)
{
    extern __shared__ char smem[];

    if (cntPtr) M = __ldg(cntPtr);
    const int row0 = blockIdx.y * 256;
    if (row0 >= M) return;
    const int col0 = blockIdx.x * 128;

    const int tid  = threadIdx.x;
    const int lane = tid & 31;
    const int wid  = tid >> 5;      // 0..15
    const int wm   = wid >> 2;      // 0..3 (m offset wm*64)
    const int wn   = wid & 3;       // 0..3 (n offset wn*32)

    const uint32_t smem_base = smem_u32(smem);

    // producer mapping: A 256x32 bf16 per plane = 1024 16B-units; 2/thread
    const int rA  = tid >> 1;          // 0..255
    const int uA0 = (tid & 1) << 1;
    // B 32x128 per plane = 512 units; 1/thread
    const int kB  = tid >> 4;          // 0..31
    const int uB  = tid & 15;

    const int mA = row0 + rA;
    const int aOk = (mA < M) ? 16 : 0;
    const int gA = (mA < M) ? (gatherIdx ? gatherIdx[mA] : mA) : 0;
    const __nv_bfloat16* aSrcH = Ah_g + (long long)gA * K;
    const __nv_bfloat16* aSrcL = Al_g + (long long)gA * K;

    const int nchunk = K / CHUNK_K;

#define PREFETCH(c) do {                                                         \
        int _b = (c) % NBUF;                                                     \
        int _k0 = (c) * CHUNK_K;                                                 \
        uint32_t _base = smem_base + _b * BUF_BYTES;                             \
        _Pragma("unroll")                                                        \
        for (int _p = 0; _p < 2; _p++) {                                         \
            int _u = uA0 + _p;                                                   \
            uint32_t _d = _base + rA * 64 + ((_u ^ (rA & 3)) << 4);              \
            cp_async16(_d,           aSrcH + _k0 + _u * 8, aOk);                 \
            cp_async16(_d + A_PLANE, aSrcL + _k0 + _u * 8, aOk);                 \
        }                                                                        \
        {                                                                        \
            uint32_t _d = _base + B_BASE + kB * 256 + ((uB ^ (kB & 7)) << 4);    \
            long long _go = (long long)(_k0 + kB) * N + col0 + uB * 8;           \
            cp_async16(_d,           Bh_g + _go, 16);                            \
            cp_async16(_d + B_PLANE, Bl_g + _go, 16);                            \
        }                                                                        \
        CP_COMMIT();                                                             \
    } while (0)

    // ldmatrix lane addressing
    const int rowA  = wm * 64 + (lane & 7) + ((lane >> 3) & 1) * 8;
    const int kbA   = (lane >> 4) & 1;
    const int swzA  = rowA & 3;
    const int kBld  = (lane & 7) + ((lane >> 3) & 1) * 8;
    const int nbB   = (lane >> 4) & 1;
    const int kswzB = kBld & 7;

    float acc[4][4][4];
#pragma unroll
    for (int mi = 0; mi < 4; mi++)
#pragma unroll
        for (int nj = 0; nj < 4; nj++)
#pragma unroll
            for (int q = 0; q < 4; q++) acc[mi][nj][q] = 0.f;

    PREFETCH(0);
    PREFETCH(1);

    for (int c = 0; c < nchunk; c++) {
        if (c + 1 < nchunk) { CP_WAIT(1); } else { CP_WAIT(0); }
        __syncthreads();
        if (c + 2 < nchunk) PREFETCH(c + 2);

        const int b = c % NBUF;
        const uint32_t bufAh = smem_base + b * BUF_BYTES;
        const uint32_t bufAl = bufAh + A_PLANE;
        const uint32_t bufBh = bufAh + B_BASE;
        const uint32_t bufBl = bufBh + B_PLANE;

#pragma unroll
        for (int ks = 0; ks < 2; ks++) {
            uint32_t bh[2][4], bl[2][4];
#pragma unroll
            for (int j = 0; j < 2; j++) {
                int nchk = wn * 4 + j * 2 + nbB;
                uint32_t boff = (uint32_t)((kBld + ks * 16) * 256 +
                                ((nchk ^ kswzB) << 4));
                ldsm_x4_t(bh[j], bufBh + boff);
                ldsm_x4_t(bl[j], bufBl + boff);
            }
#pragma unroll
            for (int mi = 0; mi < 4; mi++) {
                uint32_t ah[4], al[4];
                uint32_t aoff = (uint32_t)((rowA + mi * 16) * 64 +
                                (((ks * 2 + kbA) ^ swzA) << 4));
                ldsm_x4(ah, bufAh + aoff);
                ldsm_x4(al, bufAl + aoff);
#pragma unroll
                for (int nj = 0; nj < 4; nj++) {
                    int j = nj >> 1, p = (nj & 1) * 2;
                    uint32_t b0h = bh[j][p], b1h = bh[j][p + 1];
                    uint32_t b0l = bl[j][p], b1l = bl[j][p + 1];
                    mma16816(acc[mi][nj], ah[0], ah[1], ah[2], ah[3], b0h, b1h);
                    mma16816(acc[mi][nj], ah[0], ah[1], ah[2], ah[3], b0l, b1l);
                    mma16816(acc[mi][nj], al[0], al[1], al[2], al[3], b0h, b1h);
                }
            }
        }
    }

    // ---------------- epilogue ----------------
    const int colBase = col0 + wn * 32 + (lane & 3) * 2;
#pragma unroll
    for (int mi = 0; mi < 4; mi++) {
        int r0 = row0 + wm * 64 + mi * 16 + (lane >> 2);
        int r1 = r0 + 8;
        if (scatterIdx) {
            int g0 = 0, g1 = 0; float w0 = 0.f, w1 = 0.f;
            bool v0 = r0 < M, v1 = r1 < M;
            if (v0) { g0 = scatterIdx[r0]; w0 = scatterW[r0]; }
            if (v1) { g1 = scatterIdx[r1]; w1 = scatterW[r1]; }
#pragma unroll
            for (int nj = 0; nj < 4; nj++) {
                int col = colBase + nj * 8;
                float b0 = bias ? bias[col] : 0.f;
                float b1 = bias ? bias[col + 1] : 0.f;
                if (v0) {
                    float* p = Cf + (long long)g0 * N + col;
                    p[0] += w0 * (acc[mi][nj][0] + b0);
                    p[1] += w0 * (acc[mi][nj][1] + b1);
                }
                if (v1) {
                    float* p = Cf + (long long)g1 * N + col;
                    p[0] += w1 * (acc[mi][nj][2] + b0);
                    p[1] += w1 * (acc[mi][nj][3] + b1);
                }
            }
        } else {
#pragma unroll
            for (int nj = 0; nj < 4; nj++) {
                int col = colBase + nj * 8;
                float b0 = bias ? bias[col] : 0.f;
                float b1 = bias ? bias[col + 1] : 0.f;
                float v00 = acc[mi][nj][0] + b0;
                float v01 = acc[mi][nj][1] + b1;
                float v10 = acc[mi][nj][2] + b0;
                float v11 = acc[mi][nj][3] + b1;
                if (doRelu) {
                    v00 = fmaxf(v00, 0.f); v01 = fmaxf(v01, 0.f);
                    v10 = fmaxf(v10, 0.f); v11 = fmaxf(v11, 0.f);
                }
                if (r0 < M) {
                    long long o = (long long)r0 * N + col;
                    if (Cf) { Cf[o] = v00; Cf[o + 1] = v01; }
                    if (Oh) {
                        uint32_t hp, lp; split2(v00, v01, hp, lp);
                        *reinterpret_cast<uint32_t*>(Oh + o) = hp;
                        *reinterpret_cast<uint32_t*>(Ol + o) = lp;
                    }
                }
                if (r1 < M) {
                    long long o = (long long)r1 * N + col;
                    if (Cf) { Cf[o] = v10; Cf[o + 1] = v11; }
                    if (Oh) {
                        uint32_t hp, lp; split2(v10, v11, hp, lp);
                        *reinterpret_cast<uint32_t*>(Oh + o) = hp;
                        *reinterpret_cast<uint32_t*>(Ol + o) = lp;
                    }
                }
            }
        }
    }
#undef PREFETCH
}

// ---------------- gating ----------------
__global__ void __launch_bounds__(256)
gate_kernel(const float* __restrict__ h, const float* __restrict__ Wg,
            int* __restrict__ cnt, int* __restrict__ bidx, float* __restrict__ bw)
{
    __shared__ float sWg[DDIM * NEXP];
    const int tid = threadIdx.x;
    for (int i = tid; i < DDIM * NEXP; i += 256) sWg[i] = Wg[i];
    __syncthreads();

    const int warp = tid >> 5;
    const int lane = tid & 31;
    const int token = blockIdx.x * 8 + warp;
    if (token >= NTOK) return;

    float accv[NEXP];
#pragma unroll
    for (int e = 0; e < NEXP; e++) accv[e] = 0.f;
    const float* hrow = h + (long long)token * DDIM;
    for (int d = lane; d < DDIM; d += 32) {
        float hv = hrow[d];
#pragma unroll
        for (int e = 0; e < NEXP; e++)
            accv[e] = fmaf(hv, sWg[d * NEXP + e], accv[e]);
    }
#pragma unroll
    for (int e = 0; e < NEXP; e++) {
#pragma unroll
        for (int off = 16; off > 0; off >>= 1)
            accv[e] += __shfl_xor_sync(0xffffffffu, accv[e], off);
    }
    if (lane == 0) {
        int i1 = 0; float l1 = accv[0];
#pragma unroll
        for (int e = 1; e < NEXP; e++)
            if (accv[e] > l1) { l1 = accv[e]; i1 = e; }
        int i2 = -1; float l2 = -3.0e38f;
#pragma unroll
        for (int e = 0; e < NEXP; e++)
            if (e != i1 && accv[e] > l2) { l2 = accv[e]; i2 = e; }
        float p2 = expf(l2 - l1);
        float w1 = 1.f / (1.f + p2);
        float w2 = p2 * w1;
        int p = atomicAdd(&cnt[i1], 1);
        bidx[i1 * NTOK + p] = token; bw[i1 * NTOK + p] = w1;
        p = atomicAdd(&cnt[i2], 1);
        bidx[i2 * NTOK + p] = token; bw[i2 * NTOK + p] = w2;
    }
}

// ---------------- launch ----------------
extern "C" void kernel_launch(void* const* d_in, const int* in_sizes, int n_in,
                              void* d_out, int out_size)
{
    const float* x      = (const float*)d_in[0];
    const float* W_in   = (const float*)d_in[1];
    const float* b_in   = (const float*)d_in[2];
    const float* W_gate = (const float*)d_in[3];
    const float* W1     = (const float*)d_in[4];
    const float* b1     = (const float*)d_in[5];
    const float* W2     = (const float*)d_in[6];
    const float* b2     = (const float*)d_in[7];
    const float* W_head = (const float*)d_in[8];
    float* out = (float*)d_out;

    float *h_p, *moe_p, *bw_p;
    int *cnt_p, *bidx_p;
    __nv_bfloat16 *xh, *xl, *hh, *hl, *heh, *hel, *mh, *ml;
    __nv_bfloat16 *wih, *wil, *w1h, *w1l, *w2h, *w2l, *whh, *whl;
    cudaGetSymbolAddress((void**)&h_p,   g_h);
    cudaGetSymbolAddress((void**)&moe_p, g_moe);
    cudaGetSymbolAddress((void**)&cnt_p, g_cnt);
    cudaGetSymbolAddress((void**)&bidx_p,g_bidx);
    cudaGetSymbolAddress((void**)&bw_p,  g_bw);
    cudaGetSymbolAddress((void**)&xh,  g_xh);  cudaGetSymbolAddress((void**)&xl,  g_xl);
    cudaGetSymbolAddress((void**)&hh,  g_hh);  cudaGetSymbolAddress((void**)&hl,  g_hl);
    cudaGetSymbolAddress((void**)&heh, g_heh); cudaGetSymbolAddress((void**)&hel, g_hel);
    cudaGetSymbolAddress((void**)&mh,  g_mh);  cudaGetSymbolAddress((void**)&ml,  g_ml);
    cudaGetSymbolAddress((void**)&wih, g_wih); cudaGetSymbolAddress((void**)&wil, g_wil);
    cudaGetSymbolAddress((void**)&w1h, g_w1h); cudaGetSymbolAddress((void**)&w1l, g_w1l);
    cudaGetSymbolAddress((void**)&w2h, g_w2h); cudaGetSymbolAddress((void**)&w2l, g_w2l);
    cudaGetSymbolAddress((void**)&whh, g_whh); cudaGetSymbolAddress((void**)&whl, g_whl);

    cudaFuncSetAttribute(tc_gemm2,
                         cudaFuncAttributeMaxDynamicSharedMemorySize, SMEM_TOTAL);

    // launch order arranged so the big GEMM is launch #6 (ncu -s 5 -c 1)
    zero_i_kernel<<<1, 32>>>(cnt_p, NEXP);                                     // 1
    zero_f4_kernel<<<1024, 256>>>(moe_p, (long long)NTOK * DDIM / 4);          // 2
    split_kernel<<<2048, 256>>>(x,      xh,  xl,  (long long)NTOK * DDIM / 4); // 3
    split_kernel<<<512,  256>>>(W_in,   wih, wil, (long long)DDIM * DDIM / 4); // 4
    split_kernel<<<1024, 256>>>(W_head, whh, whl, (long long)DDIM * DOUT / 4); // 5

    // h = x @ W_in + b_in  -> fp32 (gate) + split planes                       // 6
    tc_gemm2<<<dim3(DDIM / 128, NTOK / 256), 512, SMEM_TOTAL>>>(
        xh, xl, wih, wil, h_p, hh, hl, b_in,
        nullptr, nullptr, nullptr, nullptr, NTOK, DDIM, DDIM, 0);

    gate_kernel<<<NTOK / 8, 256>>>(h_p, W_gate, cnt_p, bidx_p, bw_p);

    split_kernel<<<4096, 256>>>(W1, w1h, w1l, (long long)NEXP * DDIM * HDIM / 4);
    split_kernel<<<4096, 256>>>(W2, w2h, w2l, (long long)NEXP * HDIM * DDIM / 4);

    for (int e = 0; e < NEXP; e++) {
        tc_gemm2<<<dim3(HDIM / 128, NTOK / 256), 512, SMEM_TOTAL>>>(
            hh, hl, w1h + (size_t)e * DDIM * HDIM, w1l + (size_t)e * DDIM * HDIM,
            nullptr, heh, hel, b1 + (size_t)e * HDIM,
            bidx_p + e * NTOK, nullptr, nullptr, cnt_p + e,
            NTOK, HDIM, DDIM, 1);
        tc_gemm2<<<dim3(DDIM / 128, NTOK / 256), 512, SMEM_TOTAL>>>(
            heh, hel, w2h + (size_t)e * HDIM * DDIM, w2l + (size_t)e * HDIM * DDIM,
            moe_p, nullptr, nullptr, b2 + (size_t)e * DDIM,
            nullptr, bidx_p + e * NTOK, bw_p + e * NTOK, cnt_p + e,
            NTOK, DDIM, HDIM, 0);
    }

    split_kernel<<<2048, 256>>>(moe_p, mh, ml, (long long)NTOK * DDIM / 4);
    tc_gemm2<<<dim3(DOUT / 128, NTOK / 256), 512, SMEM_TOTAL>>>(
        mh, ml, whh, whl, out, nullptr, nullptr, nullptr,
        nullptr, nullptr, nullptr, nullptr, NTOK, DOUT, DDIM, 0);
}

// round 6
// speedup vs baseline: 3.0196x; 1.0940x over previous
#include <cuda_runtime.h>
#include <cuda_bf16.h>
#include <cstdint>
#include <math.h>

// Problem constants
#define NTOK 16384
#define DDIM 1024
#define HDIM 4096
#define NEXP 8
#define DOUT 4096
#define NSLOT (2 * NTOK)     // exactly 2 bucket entries per token

// ---------------- scratch (no allocations allowed) ----------------
__device__ float g_h[(size_t)NTOK * DDIM];        // h fp32 (gate input)
__device__ float g_ys[(size_t)NSLOT * DDIM];      // per-slot expert output fp32
__device__ int   g_cnt[NEXP];
__device__ int   g_base[NEXP];
__device__ int   g_bidx[NEXP * NTOK];
__device__ int2  g_tokE[NTOK];                    // per-token top-2 expert ids
__device__ int2  g_tokP[NTOK];                    // per-token bucket positions
__device__ float2 g_tokW[NTOK];                   // per-token weights

// split-bf16 planes (hi / lo)
__device__ __nv_bfloat16 g_xh[(size_t)NTOK * DDIM],  g_xl[(size_t)NTOK * DDIM];
__device__ __nv_bfloat16 g_hh[(size_t)NTOK * DDIM],  g_hl[(size_t)NTOK * DDIM];
__device__ __nv_bfloat16 g_heh[(size_t)NSLOT * HDIM], g_hel[(size_t)NSLOT * HDIM];
__device__ __nv_bfloat16 g_mh[(size_t)NTOK * DDIM],  g_ml[(size_t)NTOK * DDIM];
__device__ __nv_bfloat16 g_wih[(size_t)DDIM * DDIM], g_wil[(size_t)DDIM * DDIM];
__device__ __nv_bfloat16 g_w1h[(size_t)NEXP * DDIM * HDIM], g_w1l[(size_t)NEXP * DDIM * HDIM];
__device__ __nv_bfloat16 g_w2h[(size_t)NEXP * HDIM * DDIM], g_w2l[(size_t)NEXP * HDIM * DDIM];
__device__ __nv_bfloat16 g_whh[(size_t)DDIM * DOUT], g_whl[(size_t)DDIM * DOUT];

// ---------------- helpers ----------------
static __device__ __forceinline__ uint32_t smem_u32(const void* p) {
    uint32_t a;
    asm("{ .reg .u64 t; cvta.to.shared.u64 t, %1; cvt.u32.u64 %0, t; }"
        : "=r"(a) : "l"(p));
    return a;
}
static __device__ __forceinline__ void cp_async16(uint32_t dst, const void* src, int srcBytes) {
    asm volatile("cp.async.cg.shared.global [%0], [%1], %2, %3;"
                 :: "r"(dst), "l"(src), "n"(16), "r"(srcBytes) : "memory");
}
#define CP_COMMIT() asm volatile("cp.async.commit_group;" ::: "memory")
#define CP_WAIT(n)  asm volatile("cp.async.wait_group %0;" :: "n"(n) : "memory")

static __device__ __forceinline__ void ldsm_x4(uint32_t (&r)[4], uint32_t addr) {
    asm volatile("ldmatrix.sync.aligned.m8n8.x4.shared.b16 {%0,%1,%2,%3}, [%4];"
                 : "=r"(r[0]), "=r"(r[1]), "=r"(r[2]), "=r"(r[3]) : "r"(addr));
}
static __device__ __forceinline__ void ldsm_x4_t(uint32_t (&r)[4], uint32_t addr) {
    asm volatile("ldmatrix.sync.aligned.m8n8.x4.trans.shared.b16 {%0,%1,%2,%3}, [%4];"
                 : "=r"(r[0]), "=r"(r[1]), "=r"(r[2]), "=r"(r[3]) : "r"(addr));
}
static __device__ __forceinline__ void mma16816(float (&d)[4],
    uint32_t a0, uint32_t a1, uint32_t a2, uint32_t a3, uint32_t b0, uint32_t b1)
{
    asm volatile("mma.sync.aligned.m16n8k16.row.col.f32.bf16.bf16.f32 "
                 "{%0,%1,%2,%3}, {%4,%5,%6,%7}, {%8,%9}, {%0,%1,%2,%3};"
                 : "+f"(d[0]), "+f"(d[1]), "+f"(d[2]), "+f"(d[3])
                 : "r"(a0), "r"(a1), "r"(a2), "r"(a3), "r"(b0), "r"(b1));
}
static __device__ __forceinline__ void split2(float a, float b, uint32_t& h, uint32_t& l) {
    __nv_bfloat162 hb = __float22bfloat162_rn(make_float2(a, b));
    float ra = a - __bfloat162float(hb.x);
    float rb = b - __bfloat162float(hb.y);
    __nv_bfloat162 lb = __float22bfloat162_rn(make_float2(ra, rb));
    h = *reinterpret_cast<uint32_t*>(&hb);
    l = *reinterpret_cast<uint32_t*>(&lb);
}

// ---------------- smem layout ----------------
#define CHUNK_K    32
#define A_PLANE    16384
#define B_PLANE    8192
#define B_BASE     (2 * A_PLANE)
#define BUF_BYTES  (2 * A_PLANE + 2 * B_PLANE)
#define NBUF       3
#define SMEM_TOTAL (NBUF * BUF_BYTES)

// ---------------- small kernels ----------------
__global__ void zero_i_kernel(int* p, int n) {
    int i = blockIdx.x * blockDim.x + threadIdx.x;
    if (i < n) p[i] = 0;
}
__global__ void split_kernel(const float* __restrict__ src,
                             __nv_bfloat16* __restrict__ dh,
                             __nv_bfloat16* __restrict__ dl, long long n4)
{
    long long i = blockIdx.x * (long long)blockDim.x + threadIdx.x;
    long long stride = (long long)gridDim.x * blockDim.x;
    for (; i < n4; i += stride) {
        float4 v = reinterpret_cast<const float4*>(src)[i];
        uint32_t h0, l0, h1, l1;
        split2(v.x, v.y, h0, l0);
        split2(v.z, v.w, h1, l1);
        reinterpret_cast<uint2*>(dh)[i] = make_uint2(h0, h1);
        reinterpret_cast<uint2*>(dl)[i] = make_uint2(l0, l1);
    }
}
__global__ void prefix_kernel(const int* __restrict__ cnt, int* __restrict__ base) {
    if (threadIdx.x == 0) {
        int s = 0;
#pragma unroll
        for (int e = 0; e < NEXP; e++) { base[e] = s; s += cnt[e]; }
    }
}
// moe[t] = w0*y[s0] + w1*y[s1]  -> split planes directly
__global__ void __launch_bounds__(256)
combine_kernel(const float* __restrict__ ys, const int* __restrict__ base,
               const int2* __restrict__ tokE, const int2* __restrict__ tokP,
               const float2* __restrict__ tokW,
               __nv_bfloat16* __restrict__ mh, __nv_bfloat16* __restrict__ ml)
{
    const int t = blockIdx.x;
    int2 te = tokE[t];
    int2 tp = tokP[t];
    float2 tw = tokW[t];
    long long s0 = (long long)(base[te.x] + tp.x) * DDIM;
    long long s1 = (long long)(base[te.y] + tp.y) * DDIM;
    int c = threadIdx.x * 4;
    float4 y0 = *reinterpret_cast<const float4*>(ys + s0 + c);
    float4 y1 = *reinterpret_cast<const float4*>(ys + s1 + c);
    float4 v;
    v.x = tw.x * y0.x + tw.y * y1.x;
    v.y = tw.x * y0.y + tw.y * y1.y;
    v.z = tw.x * y0.z + tw.y * y1.z;
    v.w = tw.x * y0.w + tw.y * y1.w;
    uint32_t h0, l0, h1, l1;
    split2(v.x, v.y, h0, l0);
    split2(v.z, v.w, h1, l1);
    long long o = ((long long)t * DDIM + c) >> 1;
    reinterpret_cast<uint2*>(mh)[o >> 1] = make_uint2(h0, h1);
    reinterpret_cast<uint2*>(ml)[o >> 1] = make_uint2(l0, l1);
}

// ---------------- unified split-bf16 tensor-core GEMM ----------------
// grid.z = expert (or 1). M = cntPtr ? cnt[z] : Mfix. Output row = base[z] + m.
// A row source: gatherIdx ? gatherIdx[z*NTOK+m] : base[z] + m.
// B = Bh + z*bStride. bias = bias + z*N.
// Outputs: Cf fp32 and/or Oh/Ol split-bf16 (relu applied before both if doRelu).
__global__ void __launch_bounds__(512, 1)
tc_gemm(const __nv_bfloat16* __restrict__ Ah_g, const __nv_bfloat16* __restrict__ Al_g,
        const __nv_bfloat16* __restrict__ Bh_g, const __nv_bfloat16* __restrict__ Bl_g,
        size_t bStride,
        float* __restrict__ Cf,
        __nv_bfloat16* __restrict__ Oh, __nv_bfloat16* __restrict__ Ol,
        const float* __restrict__ bias,
        const int* __restrict__ gatherIdx,
        const int* __restrict__ cntPtr, const int* __restrict__ basePtr,
        int Mfix, int N, int K, int doRelu)
{
    extern __shared__ char smem[];

    const int z = blockIdx.z;
    int M = cntPtr ? __ldg(cntPtr + z) : Mfix;
    const int obase = basePtr ? __ldg(basePtr + z) : 0;
    const int row0 = blockIdx.y * 256;
    if (row0 >= M) return;
    const int col0 = blockIdx.x * 128;

    const int tid  = threadIdx.x;
    const int lane = tid & 31;
    const int wid  = tid >> 5;
    const int wm   = wid >> 2;
    const int wn   = wid & 3;

    const uint32_t smem_base = smem_u32(smem);

    const __nv_bfloat16* Bh_e = Bh_g + (size_t)z * bStride;
    const __nv_bfloat16* Bl_e = Bl_g + (size_t)z * bStride;
    const float* bias_e = bias ? bias + (size_t)z * N : nullptr;
    const int* gIdx = gatherIdx ? gatherIdx + (size_t)z * NTOK : nullptr;

    // producer mapping
    const int rA  = tid >> 1;
    const int uA0 = (tid & 1) << 1;
    const int kB  = tid >> 4;
    const int uB  = tid & 15;

    const int mA = row0 + rA;
    const int aOk = (mA < M) ? 16 : 0;
    const int gA = (mA < M) ? (gIdx ? gIdx[mA] : obase + mA) : 0;
    const __nv_bfloat16* aSrcH = Ah_g + (long long)gA * K;
    const __nv_bfloat16* aSrcL = Al_g + (long long)gA * K;

    const int nchunk = K / CHUNK_K;

#define PREFETCH(c) do {                                                         \
        int _b = (c) % NBUF;                                                     \
        int _k0 = (c) * CHUNK_K;                                                 \
        uint32_t _base = smem_base + _b * BUF_BYTES;                             \
        _Pragma("unroll")                                                        \
        for (int _p = 0; _p < 2; _p++) {                                         \
            int _u = uA0 + _p;                                                   \
            uint32_t _d = _base + rA * 64 + ((_u ^ (rA & 3)) << 4);              \
            cp_async16(_d,           aSrcH + _k0 + _u * 8, aOk);                 \
            cp_async16(_d + A_PLANE, aSrcL + _k0 + _u * 8, aOk);                 \
        }                                                                        \
        {                                                                        \
            uint32_t _d = _base + B_BASE + kB * 256 + ((uB ^ (kB & 7)) << 4);    \
            long long _go = (long long)(_k0 + kB) * N + col0 + uB * 8;           \
            cp_async16(_d,           Bh_e + _go, 16);                            \
            cp_async16(_d + B_PLANE, Bl_e + _go, 16);                            \
        }                                                                        \
        CP_COMMIT();                                                             \
    } while (0)

    const int rowA  = wm * 64 + (lane & 7) + ((lane >> 3) & 1) * 8;
    const int kbA   = (lane >> 4) & 1;
    const int swzA  = rowA & 3;
    const int kBld  = (lane & 7) + ((lane >> 3) & 1) * 8;
    const int nbB   = (lane >> 4) & 1;
    const int kswzB = kBld & 7;

    float acc[4][4][4];
#pragma unroll
    for (int mi = 0; mi < 4; mi++)
#pragma unroll
        for (int nj = 0; nj < 4; nj++)
#pragma unroll
            for (int q = 0; q < 4; q++) acc[mi][nj][q] = 0.f;

    PREFETCH(0);
    PREFETCH(1);

    for (int c = 0; c < nchunk; c++) {
        if (c + 1 < nchunk) { CP_WAIT(1); } else { CP_WAIT(0); }
        __syncthreads();
        if (c + 2 < nchunk) PREFETCH(c + 2);

        const int b = c % NBUF;
        const uint32_t bufAh = smem_base + b * BUF_BYTES;
        const uint32_t bufAl = bufAh + A_PLANE;
        const uint32_t bufBh = bufAh + B_BASE;
        const uint32_t bufBl = bufBh + B_PLANE;

#pragma unroll
        for (int ks = 0; ks < 2; ks++) {
            uint32_t bh[2][4], bl[2][4];
#pragma unroll
            for (int j = 0; j < 2; j++) {
                int nchk = wn * 4 + j * 2 + nbB;
                uint32_t boff = (uint32_t)((kBld + ks * 16) * 256 +
                                ((nchk ^ kswzB) << 4));
                ldsm_x4_t(bh[j], bufBh + boff);
                ldsm_x4_t(bl[j], bufBl + boff);
            }
#pragma unroll
            for (int mi = 0; mi < 4; mi++) {
                uint32_t ah[4], al[4];
                uint32_t aoff = (uint32_t)((rowA + mi * 16) * 64 +
                                (((ks * 2 + kbA) ^ swzA) << 4));
                ldsm_x4(ah, bufAh + aoff);
                ldsm_x4(al, bufAl + aoff);
#pragma unroll
                for (int nj = 0; nj < 4; nj++) {
                    int j = nj >> 1, p = (nj & 1) * 2;
                    uint32_t b0h = bh[j][p], b1h = bh[j][p + 1];
                    uint32_t b0l = bl[j][p], b1l = bl[j][p + 1];
                    mma16816(acc[mi][nj], ah[0], ah[1], ah[2], ah[3], b0h, b1h);
                    mma16816(acc[mi][nj], ah[0], ah[1], ah[2], ah[3], b0l, b1l);
                    mma16816(acc[mi][nj], al[0], al[1], al[2], al[3], b0h, b1h);
                }
            }
        }
    }

    // ---------------- epilogue ----------------
    const int colBase = col0 + wn * 32 + (lane & 3) * 2;
#pragma unroll
    for (int mi = 0; mi < 4; mi++) {
        int r0 = row0 + wm * 64 + mi * 16 + (lane >> 2);
        int r1 = r0 + 8;
#pragma unroll
        for (int nj = 0; nj < 4; nj++) {
            int col = colBase + nj * 8;
            float b0 = bias_e ? bias_e[col] : 0.f;
            float b1 = bias_e ? bias_e[col + 1] : 0.f;
            float v00 = acc[mi][nj][0] + b0;
            float v01 = acc[mi][nj][1] + b1;
            float v10 = acc[mi][nj][2] + b0;
            float v11 = acc[mi][nj][3] + b1;
            if (doRelu) {
                v00 = fmaxf(v00, 0.f); v01 = fmaxf(v01, 0.f);
                v10 = fmaxf(v10, 0.f); v11 = fmaxf(v11, 0.f);
            }
            if (r0 < M) {
                long long o = (long long)(obase + r0) * N + col;
                if (Cf) { Cf[o] = v00; Cf[o + 1] = v01; }
                if (Oh) {
                    uint32_t hp, lp; split2(v00, v01, hp, lp);
                    *reinterpret_cast<uint32_t*>(Oh + o) = hp;
                    *reinterpret_cast<uint32_t*>(Ol + o) = lp;
                }
            }
            if (r1 < M) {
                long long o = (long long)(obase + r1) * N + col;
                if (Cf) { Cf[o] = v10; Cf[o + 1] = v11; }
                if (Oh) {
                    uint32_t hp, lp; split2(v10, v11, hp, lp);
                    *reinterpret_cast<uint32_t*>(Oh + o) = hp;
                    *reinterpret_cast<uint32_t*>(Ol + o) = lp;
                }
            }
        }
    }
#undef PREFETCH
}

// ---------------- gating ----------------
__global__ void __launch_bounds__(256)
gate_kernel(const float* __restrict__ h, const float* __restrict__ Wg,
            int* __restrict__ cnt, int* __restrict__ bidx,
            int2* __restrict__ tokE, int2* __restrict__ tokP,
            float2* __restrict__ tokW)
{
    __shared__ float sWg[DDIM * NEXP];
    const int tid = threadIdx.x;
    for (int i = tid; i < DDIM * NEXP; i += 256) sWg[i] = Wg[i];
    __syncthreads();

    const int warp = tid >> 5;
    const int lane = tid & 31;
    const int token = blockIdx.x * 8 + warp;
    if (token >= NTOK) return;

    float accv[NEXP];
#pragma unroll
    for (int e = 0; e < NEXP; e++) accv[e] = 0.f;
    const float* hrow = h + (long long)token * DDIM;
    for (int d = lane; d < DDIM; d += 32) {
        float hv = hrow[d];
#pragma unroll
        for (int e = 0; e < NEXP; e++)
            accv[e] = fmaf(hv, sWg[d * NEXP + e], accv[e]);
    }
#pragma unroll
    for (int e = 0; e < NEXP; e++) {
#pragma unroll
        for (int off = 16; off > 0; off >>= 1)
            accv[e] += __shfl_xor_sync(0xffffffffu, accv[e], off);
    }
    if (lane == 0) {
        int i1 = 0; float l1 = accv[0];
#pragma unroll
        for (int e = 1; e < NEXP; e++)
            if (accv[e] > l1) { l1 = accv[e]; i1 = e; }
        int i2 = -1; float l2 = -3.0e38f;
#pragma unroll
        for (int e = 0; e < NEXP; e++)
            if (e != i1 && accv[e] > l2) { l2 = accv[e]; i2 = e; }
        float p2 = expf(l2 - l1);
        float w1 = 1.f / (1.f + p2);
        float w2 = p2 * w1;
        int p = atomicAdd(&cnt[i1], 1);
        bidx[i1 * NTOK + p] = token;
        int q = atomicAdd(&cnt[i2], 1);
        bidx[i2 * NTOK + q] = token;
        tokE[token] = make_int2(i1, i2);
        tokP[token] = make_int2(p, q);
        tokW[token] = make_float2(w1, w2);
    }
}

// ---------------- launch ----------------
extern "C" void kernel_launch(void* const* d_in, const int* in_sizes, int n_in,
                              void* d_out, int out_size)
{
    const float* x      = (const float*)d_in[0];
    const float* W_in   = (const float*)d_in[1];
    const float* b_in   = (const float*)d_in[2];
    const float* W_gate = (const float*)d_in[3];
    const float* W1     = (const float*)d_in[4];
    const float* b1     = (const float*)d_in[5];
    const float* W2     = (const float*)d_in[6];
    const float* b2     = (const float*)d_in[7];
    const float* W_head = (const float*)d_in[8];
    float* out = (float*)d_out;

    float *h_p, *ys_p;
    int *cnt_p, *base_p, *bidx_p;
    int2 *tokE_p, *tokP_p;
    float2 *tokW_p;
    __nv_bfloat16 *xh, *xl, *hh, *hl, *heh, *hel, *mh, *ml;
    __nv_bfloat16 *wih, *wil, *w1h, *w1l, *w2h, *w2l, *whh, *whl;
    cudaGetSymbolAddress((void**)&h_p,   g_h);
    cudaGetSymbolAddress((void**)&ys_p,  g_ys);
    cudaGetSymbolAddress((void**)&cnt_p, g_cnt);
    cudaGetSymbolAddress((void**)&base_p,g_base);
    cudaGetSymbolAddress((void**)&bidx_p,g_bidx);
    cudaGetSymbolAddress((void**)&tokE_p,g_tokE);
    cudaGetSymbolAddress((void**)&tokP_p,g_tokP);
    cudaGetSymbolAddress((void**)&tokW_p,g_tokW);
    cudaGetSymbolAddress((void**)&xh,  g_xh);  cudaGetSymbolAddress((void**)&xl,  g_xl);
    cudaGetSymbolAddress((void**)&hh,  g_hh);  cudaGetSymbolAddress((void**)&hl,  g_hl);
    cudaGetSymbolAddress((void**)&heh, g_heh); cudaGetSymbolAddress((void**)&hel, g_hel);
    cudaGetSymbolAddress((void**)&mh,  g_mh);  cudaGetSymbolAddress((void**)&ml,  g_ml);
    cudaGetSymbolAddress((void**)&wih, g_wih); cudaGetSymbolAddress((void**)&wil, g_wil);
    cudaGetSymbolAddress((void**)&w1h, g_w1h); cudaGetSymbolAddress((void**)&w1l, g_w1l);
    cudaGetSymbolAddress((void**)&w2h, g_w2h); cudaGetSymbolAddress((void**)&w2l, g_w2l);
    cudaGetSymbolAddress((void**)&whh, g_whh); cudaGetSymbolAddress((void**)&whl, g_whl);

    cudaFuncSetAttribute(tc_gemm,
                         cudaFuncAttributeMaxDynamicSharedMemorySize, SMEM_TOTAL);

    zero_i_kernel<<<1, 32>>>(cnt_p, NEXP);                                      // 1
    split_kernel<<<2048, 256>>>(x,      xh,  xl,  (long long)NTOK * DDIM / 4);  // 2
    split_kernel<<<512,  256>>>(W_in,   wih, wil, (long long)DDIM * DDIM / 4);  // 3
    split_kernel<<<4096, 256>>>(W1,     w1h, w1l, (long long)NEXP * DDIM * HDIM / 4); // 4
    split_kernel<<<1024, 256>>>(W_head, whh, whl, (long long)DDIM * DOUT / 4);  // 5

    // 6: h = x @ W_in + b_in  -> fp32 + split planes
    tc_gemm<<<dim3(DDIM / 128, NTOK / 256, 1), 512, SMEM_TOTAL>>>(
        xh, xl, wih, wil, 0,
        h_p, hh, hl, b_in,
        nullptr, nullptr, nullptr, NTOK, DDIM, DDIM, 0);

    gate_kernel<<<NTOK / 8, 256>>>(h_p, W_gate, cnt_p, bidx_p, tokE_p, tokP_p, tokW_p);
    prefix_kernel<<<1, 32>>>(cnt_p, base_p);
    split_kernel<<<4096, 256>>>(W2, w2h, w2l, (long long)NEXP * HDIM * DDIM / 4);

    // up: he[base[e]+m] = relu(h[bidx[e,m]] @ W1[e] + b1[e]) -> split planes
    tc_gemm<<<dim3(HDIM / 128, NTOK / 256, NEXP), 512, SMEM_TOTAL>>>(
        hh, hl, w1h, w1l, (size_t)DDIM * HDIM,
        nullptr, heh, hel, b1,
        bidx_p, cnt_p, base_p, 0, HDIM, DDIM, 1);

    // down: ys[base[e]+m] = he[base[e]+m] @ W2[e] + b2[e]  (fp32, no scatter)
    tc_gemm<<<dim3(DDIM / 128, NTOK / 256, NEXP), 512, SMEM_TOTAL>>>(
        heh, hel, w2h, w2l, (size_t)HDIM * DDIM,
        ys_p, nullptr, nullptr, b2,
        nullptr, cnt_p, base_p, 0, DDIM, HDIM, 0);

    // combine -> split planes for head
    combine_kernel<<<NTOK, 256>>>(ys_p, base_p, tokE_p, tokP_p, tokW_p, mh, ml);

    // head: out = moe @ W_head
    tc_gemm<<<dim3(DOUT / 128, NTOK / 256, 1), 512, SMEM_TOTAL>>>(
        mh, ml, whh, whl, 0,
        out, nullptr, nullptr, nullptr,
        nullptr, nullptr, nullptr, NTOK, DOUT, DDIM, 0);
}

// round 7
// speedup vs baseline: 6.0338x; 1.9982x over previous
#include <cuda_runtime.h>
#include <cuda_bf16.h>
#include <cuda_fp16.h>
#include <cstdint>
#include <math.h>

// Problem constants
#define NTOK 16384
#define DDIM 1024
#define HDIM 4096
#define NEXP 8
#define DOUT 4096
#define NSLOT (2 * NTOK)

// ---------------- scratch (no allocations allowed) ----------------
__device__ float g_h[(size_t)NTOK * DDIM];        // h fp32 (gate input)
__device__ float g_ys[(size_t)NSLOT * DDIM];      // per-slot expert output fp32
__device__ int   g_cnt[NEXP];
__device__ int   g_base[NEXP];
__device__ int   g_bidx[NEXP * NTOK];
__device__ int2  g_tokE[NTOK];
__device__ int2  g_tokP[NTOK];
__device__ float2 g_tokW[NTOK];

// bf16 split planes (GEMM1 inputs only)
__device__ uint16_t g_xh[(size_t)NTOK * DDIM],  g_xl[(size_t)NTOK * DDIM];
__device__ uint16_t g_wih[(size_t)DDIM * DDIM], g_wil[(size_t)DDIM * DDIM];
// fp16 single planes
__device__ uint16_t g_h16[(size_t)NTOK * DDIM];
__device__ uint16_t g_he16[(size_t)NSLOT * HDIM];
__device__ uint16_t g_m16[(size_t)NTOK * DDIM];
__device__ uint16_t g_w1f[(size_t)NEXP * DDIM * HDIM];
__device__ uint16_t g_w2f[(size_t)NEXP * HDIM * DDIM];
__device__ uint16_t g_whf[(size_t)DDIM * DOUT];

// ---------------- helpers ----------------
static __device__ __forceinline__ uint32_t smem_u32(const void* p) {
    uint32_t a;
    asm("{ .reg .u64 t; cvta.to.shared.u64 t, %1; cvt.u32.u64 %0, t; }"
        : "=r"(a) : "l"(p));
    return a;
}
static __device__ __forceinline__ void cp_async16(uint32_t dst, const void* src, int srcBytes) {
    asm volatile("cp.async.cg.shared.global [%0], [%1], %2, %3;"
                 :: "r"(dst), "l"(src), "n"(16), "r"(srcBytes) : "memory");
}
#define CP_COMMIT() asm volatile("cp.async.commit_group;" ::: "memory")
#define CP_WAIT(n)  asm volatile("cp.async.wait_group %0;" :: "n"(n) : "memory")

static __device__ __forceinline__ void ldsm_x4(uint32_t (&r)[4], uint32_t addr) {
    asm volatile("ldmatrix.sync.aligned.m8n8.x4.shared.b16 {%0,%1,%2,%3}, [%4];"
                 : "=r"(r[0]), "=r"(r[1]), "=r"(r[2]), "=r"(r[3]) : "r"(addr));
}
static __device__ __forceinline__ void ldsm_x4_t(uint32_t (&r)[4], uint32_t addr) {
    asm volatile("ldmatrix.sync.aligned.m8n8.x4.trans.shared.b16 {%0,%1,%2,%3}, [%4];"
                 : "=r"(r[0]), "=r"(r[1]), "=r"(r[2]), "=r"(r[3]) : "r"(addr));
}
static __device__ __forceinline__ void mma_bf16(float (&d)[4],
    uint32_t a0, uint32_t a1, uint32_t a2, uint32_t a3, uint32_t b0, uint32_t b1)
{
    asm volatile("mma.sync.aligned.m16n8k16.row.col.f32.bf16.bf16.f32 "
                 "{%0,%1,%2,%3}, {%4,%5,%6,%7}, {%8,%9}, {%0,%1,%2,%3};"
                 : "+f"(d[0]), "+f"(d[1]), "+f"(d[2]), "+f"(d[3])
                 : "r"(a0), "r"(a1), "r"(a2), "r"(a3), "r"(b0), "r"(b1));
}
static __device__ __forceinline__ void mma_f16(float (&d)[4],
    uint32_t a0, uint32_t a1, uint32_t a2, uint32_t a3, uint32_t b0, uint32_t b1)
{
    asm volatile("mma.sync.aligned.m16n8k16.row.col.f32.f16.f16.f32 "
                 "{%0,%1,%2,%3}, {%4,%5,%6,%7}, {%8,%9}, {%0,%1,%2,%3};"
                 : "+f"(d[0]), "+f"(d[1]), "+f"(d[2]), "+f"(d[3])
                 : "r"(a0), "r"(a1), "r"(a2), "r"(a3), "r"(b0), "r"(b1));
}
static __device__ __forceinline__ void split2(float a, float b, uint32_t& h, uint32_t& l) {
    __nv_bfloat162 hb = __float22bfloat162_rn(make_float2(a, b));
    float ra = a - __bfloat162float(hb.x);
    float rb = b - __bfloat162float(hb.y);
    __nv_bfloat162 lb = __float22bfloat162_rn(make_float2(ra, rb));
    h = *reinterpret_cast<uint32_t*>(&hb);
    l = *reinterpret_cast<uint32_t*>(&lb);
}

#define CHUNK_K 32
#define NBUF    3

// ---------------- small kernels ----------------
__global__ void zero_i_kernel(int* p, int n) {
    int i = blockIdx.x * blockDim.x + threadIdx.x;
    if (i < n) p[i] = 0;
}
__global__ void split_kernel(const float* __restrict__ src,
                             uint16_t* __restrict__ dh,
                             uint16_t* __restrict__ dl, long long n4)
{
    long long i = blockIdx.x * (long long)blockDim.x + threadIdx.x;
    long long stride = (long long)gridDim.x * blockDim.x;
    for (; i < n4; i += stride) {
        float4 v = reinterpret_cast<const float4*>(src)[i];
        uint32_t h0, l0, h1, l1;
        split2(v.x, v.y, h0, l0);
        split2(v.z, v.w, h1, l1);
        reinterpret_cast<uint2*>(dh)[i] = make_uint2(h0, h1);
        reinterpret_cast<uint2*>(dl)[i] = make_uint2(l0, l1);
    }
}
__global__ void tohalf_kernel(const float* __restrict__ src,
                              uint16_t* __restrict__ dst, long long n4)
{
    long long i = blockIdx.x * (long long)blockDim.x + threadIdx.x;
    long long stride = (long long)gridDim.x * blockDim.x;
    for (; i < n4; i += stride) {
        float4 v = reinterpret_cast<const float4*>(src)[i];
        __half2 a = __floats2half2_rn(v.x, v.y);
        __half2 b = __floats2half2_rn(v.z, v.w);
        reinterpret_cast<uint2*>(dst)[i] =
            make_uint2(*reinterpret_cast<uint32_t*>(&a),
                       *reinterpret_cast<uint32_t*>(&b));
    }
}
__global__ void prefix_kernel(const int* __restrict__ cnt, int* __restrict__ base) {
    if (threadIdx.x == 0) {
        int s = 0;
#pragma unroll
        for (int e = 0; e < NEXP; e++) { base[e] = s; s += cnt[e]; }
    }
}
// moe[t] = w0*y[s0] + w1*y[s1]  -> fp16 plane
__global__ void __launch_bounds__(256)
combine_kernel(const float* __restrict__ ys, const int* __restrict__ base,
               const int2* __restrict__ tokE, const int2* __restrict__ tokP,
               const float2* __restrict__ tokW, uint16_t* __restrict__ m16)
{
    const int t = blockIdx.x;
    int2 te = tokE[t];
    int2 tp = tokP[t];
    float2 tw = tokW[t];
    long long s0 = (long long)(base[te.x] + tp.x) * DDIM;
    long long s1 = (long long)(base[te.y] + tp.y) * DDIM;
    int c = threadIdx.x * 4;
    float4 y0 = *reinterpret_cast<const float4*>(ys + s0 + c);
    float4 y1 = *reinterpret_cast<const float4*>(ys + s1 + c);
    float4 v;
    v.x = tw.x * y0.x + tw.y * y1.x;
    v.y = tw.x * y0.y + tw.y * y1.y;
    v.z = tw.x * y0.z + tw.y * y1.z;
    v.w = tw.x * y0.w + tw.y * y1.w;
    __half2 a = __floats2half2_rn(v.x, v.y);
    __half2 b = __floats2half2_rn(v.z, v.w);
    long long idx = ((long long)t * DDIM + c) >> 2;
    reinterpret_cast<uint2*>(m16)[idx] =
        make_uint2(*reinterpret_cast<uint32_t*>(&a),
                   *reinterpret_cast<uint32_t*>(&b));
}

// ---------------- unified tensor-core GEMM ----------------
// MODE 0: 3-term bf16 split (Ah/Al, Bh/Bl). MODE 1: single fp16 (Ah, Bh).
// grid.z = expert. M = cnt[z] (or Mfix). Output row = base[z] + m.
// A row m from gatherIdx[z*NTOK+m] or base[z]+m. B = Bh + z*bStride.
template<int MODE>
__global__ void __launch_bounds__(512, 1)
tc_gemm(const uint16_t* __restrict__ Ah_g, const uint16_t* __restrict__ Al_g,
        const uint16_t* __restrict__ Bh_g, const uint16_t* __restrict__ Bl_g,
        size_t bStride,
        float* __restrict__ Cf, uint16_t* __restrict__ Oh,
        const float* __restrict__ bias,
        const int* __restrict__ gatherIdx,
        const int* __restrict__ cntPtr, const int* __restrict__ basePtr,
        int Mfix, int N, int K, int doRelu)
{
    extern __shared__ char smem[];

    constexpr uint32_t APL  = 16384;                        // A plane bytes
    constexpr uint32_t BOFF = (MODE == 0) ? 32768u : 16384u;
    constexpr uint32_t BPL  = 8192;
    constexpr uint32_t BUFB = (MODE == 0) ? 49152u : 24576u;

    const int z = blockIdx.z;
    int M = cntPtr ? __ldg(cntPtr + z) : Mfix;
    const int obase = basePtr ? __ldg(basePtr + z) : 0;
    const int row0 = blockIdx.y * 256;
    if (row0 >= M) return;
    const int col0 = blockIdx.x * 128;

    const int tid  = threadIdx.x;
    const int lane = tid & 31;
    const int wid  = tid >> 5;
    const int wm   = wid >> 2;
    const int wn   = wid & 3;

    const uint32_t smem_base = smem_u32(smem);

    const uint16_t* Bh_e = Bh_g + (size_t)z * bStride;
    const uint16_t* Bl_e = (MODE == 0) ? Bl_g + (size_t)z * bStride : nullptr;
    const float* bias_e = bias ? bias + (size_t)z * N : nullptr;
    const int* gIdx = gatherIdx ? gatherIdx + (size_t)z * NTOK : nullptr;

    // producer mapping
    const int rA  = tid >> 1;
    const int uA0 = (tid & 1) << 1;
    const int kB  = tid >> 4;
    const int uB  = tid & 15;

    const int mA = row0 + rA;
    const int aOk = (mA < M) ? 16 : 0;
    const int gA = (mA < M) ? (gIdx ? gIdx[mA] : obase + mA) : 0;
    const uint16_t* aSrcH = Ah_g + (long long)gA * K;
    const uint16_t* aSrcL = (MODE == 0) ? Al_g + (long long)gA * K : nullptr;

    const int nchunk = K / CHUNK_K;

    auto prefetch = [&](int c) {
        int b = c % NBUF;
        int k0 = c * CHUNK_K;
        uint32_t base = smem_base + b * BUFB;
#pragma unroll
        for (int p = 0; p < 2; p++) {
            int u = uA0 + p;
            uint32_t d = base + rA * 64 + ((u ^ (rA & 3)) << 4);
            cp_async16(d, aSrcH + k0 + u * 8, aOk);
            if constexpr (MODE == 0)
                cp_async16(d + APL, aSrcL + k0 + u * 8, aOk);
        }
        {
            uint32_t d = base + BOFF + kB * 256 + ((uB ^ (kB & 7)) << 4);
            long long go = (long long)(k0 + kB) * N + col0 + uB * 8;
            cp_async16(d, Bh_e + go, 16);
            if constexpr (MODE == 0)
                cp_async16(d + BPL, Bl_e + go, 16);
        }
        CP_COMMIT();
    };

    const int rowA  = wm * 64 + (lane & 7) + ((lane >> 3) & 1) * 8;
    const int kbA   = (lane >> 4) & 1;
    const int swzA  = rowA & 3;
    const int kBld  = (lane & 7) + ((lane >> 3) & 1) * 8;
    const int nbB   = (lane >> 4) & 1;
    const int kswzB = kBld & 7;

    float acc[4][4][4];
#pragma unroll
    for (int mi = 0; mi < 4; mi++)
#pragma unroll
        for (int nj = 0; nj < 4; nj++)
#pragma unroll
            for (int q = 0; q < 4; q++) acc[mi][nj][q] = 0.f;

    prefetch(0);
    prefetch(1);

    for (int c = 0; c < nchunk; c++) {
        if (c + 1 < nchunk) { CP_WAIT(1); } else { CP_WAIT(0); }
        __syncthreads();
        if (c + 2 < nchunk) prefetch(c + 2);

        const int b = c % NBUF;
        const uint32_t bufAh = smem_base + b * BUFB;
        const uint32_t bufAl = bufAh + APL;
        const uint32_t bufBh = bufAh + BOFF;
        const uint32_t bufBl = bufBh + BPL;

#pragma unroll
        for (int ks = 0; ks < 2; ks++) {
            uint32_t bh[2][4], bl[2][4];
#pragma unroll
            for (int j = 0; j < 2; j++) {
                int nchk = wn * 4 + j * 2 + nbB;
                uint32_t boff = (uint32_t)((kBld + ks * 16) * 256 +
                                ((nchk ^ kswzB) << 4));
                ldsm_x4_t(bh[j], bufBh + boff);
                if constexpr (MODE == 0) ldsm_x4_t(bl[j], bufBl + boff);
            }
#pragma unroll
            for (int mi = 0; mi < 4; mi++) {
                uint32_t ah[4], al[4];
                uint32_t aoff = (uint32_t)((rowA + mi * 16) * 64 +
                                (((ks * 2 + kbA) ^ swzA) << 4));
                ldsm_x4(ah, bufAh + aoff);
                if constexpr (MODE == 0) ldsm_x4(al, bufAl + aoff);
#pragma unroll
                for (int nj = 0; nj < 4; nj++) {
                    int j = nj >> 1, p = (nj & 1) * 2;
                    uint32_t b0h = bh[j][p], b1h = bh[j][p + 1];
                    if constexpr (MODE == 0) {
                        uint32_t b0l = bl[j][p], b1l = bl[j][p + 1];
                        mma_bf16(acc[mi][nj], ah[0], ah[1], ah[2], ah[3], b0h, b1h);
                        mma_bf16(acc[mi][nj], ah[0], ah[1], ah[2], ah[3], b0l, b1l);
                        mma_bf16(acc[mi][nj], al[0], al[1], al[2], al[3], b0h, b1h);
                    } else {
                        mma_f16(acc[mi][nj], ah[0], ah[1], ah[2], ah[3], b0h, b1h);
                    }
                }
            }
        }
    }

    // ---------------- epilogue ----------------
    const int colBase = col0 + wn * 32 + (lane & 3) * 2;
#pragma unroll
    for (int mi = 0; mi < 4; mi++) {
        int r0 = row0 + wm * 64 + mi * 16 + (lane >> 2);
        int r1 = r0 + 8;
#pragma unroll
        for (int nj = 0; nj < 4; nj++) {
            int col = colBase + nj * 8;
            float b0 = bias_e ? bias_e[col] : 0.f;
            float b1 = bias_e ? bias_e[col + 1] : 0.f;
            float v00 = acc[mi][nj][0] + b0;
            float v01 = acc[mi][nj][1] + b1;
            float v10 = acc[mi][nj][2] + b0;
            float v11 = acc[mi][nj][3] + b1;
            if (doRelu) {
                v00 = fmaxf(v00, 0.f); v01 = fmaxf(v01, 0.f);
                v10 = fmaxf(v10, 0.f); v11 = fmaxf(v11, 0.f);
            }
            if (r0 < M) {
                long long o = (long long)(obase + r0) * N + col;
                if (Cf) { Cf[o] = v00; Cf[o + 1] = v01; }
                if (Oh) {
                    __half2 hv = __floats2half2_rn(v00, v01);
                    *reinterpret_cast<uint32_t*>(Oh + o) =
                        *reinterpret_cast<uint32_t*>(&hv);
                }
            }
            if (r1 < M) {
                long long o = (long long)(obase + r1) * N + col;
                if (Cf) { Cf[o] = v10; Cf[o + 1] = v11; }
                if (Oh) {
                    __half2 hv = __floats2half2_rn(v10, v11);
                    *reinterpret_cast<uint32_t*>(Oh + o) =
                        *reinterpret_cast<uint32_t*>(&hv);
                }
            }
        }
    }
}

// ---------------- gating ----------------
__global__ void __launch_bounds__(256)
gate_kernel(const float* __restrict__ h, const float* __restrict__ Wg,
            int* __restrict__ cnt, int* __restrict__ bidx,
            int2* __restrict__ tokE, int2* __restrict__ tokP,
            float2* __restrict__ tokW)
{
    __shared__ float sWg[DDIM * NEXP];
    const int tid = threadIdx.x;
    for (int i = tid; i < DDIM * NEXP; i += 256) sWg[i] = Wg[i];
    __syncthreads();

    const int warp = tid >> 5;
    const int lane = tid & 31;
    const int token = blockIdx.x * 8 + warp;
    if (token >= NTOK) return;

    float accv[NEXP];
#pragma unroll
    for (int e = 0; e < NEXP; e++) accv[e] = 0.f;
    const float* hrow = h + (long long)token * DDIM;
    for (int d = lane; d < DDIM; d += 32) {
        float hv = hrow[d];
#pragma unroll
        for (int e = 0; e < NEXP; e++)
            accv[e] = fmaf(hv, sWg[d * NEXP + e], accv[e]);
    }
#pragma unroll
    for (int e = 0; e < NEXP; e++) {
#pragma unroll
        for (int off = 16; off > 0; off >>= 1)
            accv[e] += __shfl_xor_sync(0xffffffffu, accv[e], off);
    }
    if (lane == 0) {
        int i1 = 0; float l1 = accv[0];
#pragma unroll
        for (int e = 1; e < NEXP; e++)
            if (accv[e] > l1) { l1 = accv[e]; i1 = e; }
        int i2 = -1; float l2 = -3.0e38f;
#pragma unroll
        for (int e = 0; e < NEXP; e++)
            if (e != i1 && accv[e] > l2) { l2 = accv[e]; i2 = e; }
        float p2 = expf(l2 - l1);
        float w1 = 1.f / (1.f + p2);
        float w2 = p2 * w1;
        int p = atomicAdd(&cnt[i1], 1);
        bidx[i1 * NTOK + p] = token;
        int q = atomicAdd(&cnt[i2], 1);
        bidx[i2 * NTOK + q] = token;
        tokE[token] = make_int2(i1, i2);
        tokP[token] = make_int2(p, q);
        tokW[token] = make_float2(w1, w2);
    }
}

// ---------------- launch ----------------
extern "C" void kernel_launch(void* const* d_in, const int* in_sizes, int n_in,
                              void* d_out, int out_size)
{
    const float* x      = (const float*)d_in[0];
    const float* W_in   = (const float*)d_in[1];
    const float* b_in   = (const float*)d_in[2];
    const float* W_gate = (const float*)d_in[3];
    const float* W1     = (const float*)d_in[4];
    const float* b1     = (const float*)d_in[5];
    const float* W2     = (const float*)d_in[6];
    const float* b2     = (const float*)d_in[7];
    const float* W_head = (const float*)d_in[8];
    float* out = (float*)d_out;

    float *h_p, *ys_p;
    int *cnt_p, *base_p, *bidx_p;
    int2 *tokE_p, *tokP_p;
    float2 *tokW_p;
    uint16_t *xh, *xl, *wih, *wil, *h16, *he16, *m16, *w1f, *w2f, *whf;
    cudaGetSymbolAddress((void**)&h_p,   g_h);
    cudaGetSymbolAddress((void**)&ys_p,  g_ys);
    cudaGetSymbolAddress((void**)&cnt_p, g_cnt);
    cudaGetSymbolAddress((void**)&base_p,g_base);
    cudaGetSymbolAddress((void**)&bidx_p,g_bidx);
    cudaGetSymbolAddress((void**)&tokE_p,g_tokE);
    cudaGetSymbolAddress((void**)&tokP_p,g_tokP);
    cudaGetSymbolAddress((void**)&tokW_p,g_tokW);
    cudaGetSymbolAddress((void**)&xh,  g_xh);  cudaGetSymbolAddress((void**)&xl,  g_xl);
    cudaGetSymbolAddress((void**)&wih, g_wih); cudaGetSymbolAddress((void**)&wil, g_wil);
    cudaGetSymbolAddress((void**)&h16, g_h16);
    cudaGetSymbolAddress((void**)&he16,g_he16);
    cudaGetSymbolAddress((void**)&m16, g_m16);
    cudaGetSymbolAddress((void**)&w1f, g_w1f);
    cudaGetSymbolAddress((void**)&w2f, g_w2f);
    cudaGetSymbolAddress((void**)&whf, g_whf);

    cudaFuncSetAttribute(tc_gemm<0>,
                         cudaFuncAttributeMaxDynamicSharedMemorySize, NBUF * 49152);
    cudaFuncSetAttribute(tc_gemm<1>,
                         cudaFuncAttributeMaxDynamicSharedMemorySize, NBUF * 24576);

    zero_i_kernel<<<1, 32>>>(cnt_p, NEXP);                                         // 1
    split_kernel<<<2048, 256>>>(x,    xh,  xl,  (long long)NTOK * DDIM / 4);       // 2
    split_kernel<<<512,  256>>>(W_in, wih, wil, (long long)DDIM * DDIM / 4);       // 3
    tohalf_kernel<<<4096, 256>>>(W1,     w1f, (long long)NEXP * DDIM * HDIM / 4);  // 4
    tohalf_kernel<<<1024, 256>>>(W_head, whf, (long long)DDIM * DOUT / 4);         // 5

    // 6: h = x @ W_in + b_in  -> fp32 (gate) + fp16 (up input), 3-term bf16 split
    tc_gemm<0><<<dim3(DDIM / 128, NTOK / 256, 1), 512, NBUF * 49152>>>(
        xh, xl, wih, wil, 0,
        h_p, h16, b_in,
        nullptr, nullptr, nullptr, NTOK, DDIM, DDIM, 0);

    gate_kernel<<<NTOK / 8, 256>>>(h_p, W_gate, cnt_p, bidx_p, tokE_p, tokP_p, tokW_p);
    prefix_kernel<<<1, 32>>>(cnt_p, base_p);
    tohalf_kernel<<<4096, 256>>>(W2, w2f, (long long)NEXP * HDIM * DDIM / 4);

    // up: he[base[e]+m] = relu(h16[bidx[e,m]] @ W1f[e] + b1[e]) -> fp16
    tc_gemm<1><<<dim3(HDIM / 128, NTOK / 256, NEXP), 512, NBUF * 24576>>>(
        h16, nullptr, w1f, nullptr, (size_t)DDIM * HDIM,
        nullptr, he16, b1,
        bidx_p, cnt_p, base_p, 0, HDIM, DDIM, 1);

    // down: ys[base[e]+m] = he16 @ W2f[e] + b2[e]  (fp32, contiguous)
    tc_gemm<1><<<dim3(DDIM / 128, NTOK / 256, NEXP), 512, NBUF * 24576>>>(
        he16, nullptr, w2f, nullptr, (size_t)HDIM * DDIM,
        ys_p, nullptr, b2,
        nullptr, cnt_p, base_p, 0, DDIM, HDIM, 0);

    // combine -> fp16 plane for head
    combine_kernel<<<NTOK, 256>>>(ys_p, base_p, tokE_p, tokP_p, tokW_p, m16);

    // head: out = m16 @ Whf
    tc_gemm<1><<<dim3(DOUT / 128, NTOK / 256, 1), 512, NBUF * 24576>>>(
        m16, nullptr, whf, nullptr, 0,
        out, nullptr, nullptr,
        nullptr, nullptr, nullptr, NTOK, DOUT, DDIM, 0);
}

// round 8
// speedup vs baseline: 6.8040x; 1.1277x over previous
#include <cuda_runtime.h>
#include <cuda_bf16.h>
#include <cuda_fp16.h>
#include <cstdint>
#include <math.h>

// Problem constants
#define NTOK 16384
#define DDIM 1024
#define HDIM 4096
#define NEXP 8
#define DOUT 4096
#define NSLOT (2 * NTOK)

// ---------------- scratch (no allocations allowed) ----------------
__device__ float g_h[(size_t)NTOK * DDIM];
__device__ float g_ys[(size_t)NSLOT * DDIM];
__device__ int   g_cnt[NEXP];
__device__ int   g_base[NEXP];
__device__ int   g_bidx[NEXP * NTOK];
__device__ int2  g_tokE[NTOK];
__device__ int2  g_tokP[NTOK];
__device__ float2 g_tokW[NTOK];

// bf16 split planes (GEMM1 inputs only)
__device__ uint16_t g_xh[(size_t)NTOK * DDIM],  g_xl[(size_t)NTOK * DDIM];
__device__ uint16_t g_wih[(size_t)DDIM * DDIM], g_wil[(size_t)DDIM * DDIM];
// fp16 single planes
__device__ uint16_t g_h16[(size_t)NTOK * DDIM];
__device__ uint16_t g_he16[(size_t)NSLOT * HDIM];
__device__ uint16_t g_m16[(size_t)NTOK * DDIM];
__device__ uint16_t g_w1f[(size_t)NEXP * DDIM * HDIM];
__device__ uint16_t g_w2f[(size_t)NEXP * HDIM * DDIM];
__device__ uint16_t g_whf[(size_t)DDIM * DOUT];

// ---------------- helpers ----------------
static __device__ __forceinline__ uint32_t smem_u32(const void* p) {
    uint32_t a;
    asm("{ .reg .u64 t; cvta.to.shared.u64 t, %1; cvt.u32.u64 %0, t; }"
        : "=r"(a) : "l"(p));
    return a;
}
static __device__ __forceinline__ void cp_async16(uint32_t dst, const void* src, int srcBytes) {
    asm volatile("cp.async.cg.shared.global [%0], [%1], %2, %3;"
                 :: "r"(dst), "l"(src), "n"(16), "r"(srcBytes) : "memory");
}
#define CP_COMMIT() asm volatile("cp.async.commit_group;" ::: "memory")
#define CP_WAIT(n)  asm volatile("cp.async.wait_group %0;" :: "n"(n) : "memory")

static __device__ __forceinline__ void ldsm_x4(uint32_t (&r)[4], uint32_t addr) {
    asm volatile("ldmatrix.sync.aligned.m8n8.x4.shared.b16 {%0,%1,%2,%3}, [%4];"
                 : "=r"(r[0]), "=r"(r[1]), "=r"(r[2]), "=r"(r[3]) : "r"(addr));
}
static __device__ __forceinline__ void ldsm_x4_t(uint32_t (&r)[4], uint32_t addr) {
    asm volatile("ldmatrix.sync.aligned.m8n8.x4.trans.shared.b16 {%0,%1,%2,%3}, [%4];"
                 : "=r"(r[0]), "=r"(r[1]), "=r"(r[2]), "=r"(r[3]) : "r"(addr));
}
static __device__ __forceinline__ void mma_bf16(float (&d)[4],
    uint32_t a0, uint32_t a1, uint32_t a2, uint32_t a3, uint32_t b0, uint32_t b1)
{
    asm volatile("mma.sync.aligned.m16n8k16.row.col.f32.bf16.bf16.f32 "
                 "{%0,%1,%2,%3}, {%4,%5,%6,%7}, {%8,%9}, {%0,%1,%2,%3};"
                 : "+f"(d[0]), "+f"(d[1]), "+f"(d[2]), "+f"(d[3])
                 : "r"(a0), "r"(a1), "r"(a2), "r"(a3), "r"(b0), "r"(b1));
}
static __device__ __forceinline__ void mma_f16(float (&d)[4],
    uint32_t a0, uint32_t a1, uint32_t a2, uint32_t a3, uint32_t b0, uint32_t b1)
{
    asm volatile("mma.sync.aligned.m16n8k16.row.col.f32.f16.f16.f32 "
                 "{%0,%1,%2,%3}, {%4,%5,%6,%7}, {%8,%9}, {%0,%1,%2,%3};"
                 : "+f"(d[0]), "+f"(d[1]), "+f"(d[2]), "+f"(d[3])
                 : "r"(a0), "r"(a1), "r"(a2), "r"(a3), "r"(b0), "r"(b1));
}
static __device__ __forceinline__ void split2(float a, float b, uint32_t& h, uint32_t& l) {
    __nv_bfloat162 hb = __float22bfloat162_rn(make_float2(a, b));
    float ra = a - __bfloat162float(hb.x);
    float rb = b - __bfloat162float(hb.y);
    __nv_bfloat162 lb = __float22bfloat162_rn(make_float2(ra, rb));
    h = *reinterpret_cast<uint32_t*>(&hb);
    l = *reinterpret_cast<uint32_t*>(&lb);
}

#define NBUF 3

// ---------------- small kernels ----------------
__global__ void zero_i_kernel(int* p, int n) {
    int i = blockIdx.x * blockDim.x + threadIdx.x;
    if (i < n) p[i] = 0;
}
__global__ void split_kernel(const float* __restrict__ src,
                             uint16_t* __restrict__ dh,
                             uint16_t* __restrict__ dl, long long n4)
{
    long long i = blockIdx.x * (long long)blockDim.x + threadIdx.x;
    long long stride = (long long)gridDim.x * blockDim.x;
    for (; i < n4; i += stride) {
        float4 v = reinterpret_cast<const float4*>(src)[i];
        uint32_t h0, l0, h1, l1;
        split2(v.x, v.y, h0, l0);
        split2(v.z, v.w, h1, l1);
        reinterpret_cast<uint2*>(dh)[i] = make_uint2(h0, h1);
        reinterpret_cast<uint2*>(dl)[i] = make_uint2(l0, l1);
    }
}
__global__ void tohalf_kernel(const float* __restrict__ src,
                              uint16_t* __restrict__ dst, long long n4)
{
    long long i = blockIdx.x * (long long)blockDim.x + threadIdx.x;
    long long stride = (long long)gridDim.x * blockDim.x;
    for (; i < n4; i += stride) {
        float4 v = reinterpret_cast<const float4*>(src)[i];
        __half2 a = __floats2half2_rn(v.x, v.y);
        __half2 b = __floats2half2_rn(v.z, v.w);
        reinterpret_cast<uint2*>(dst)[i] =
            make_uint2(*reinterpret_cast<uint32_t*>(&a),
                       *reinterpret_cast<uint32_t*>(&b));
    }
}
__global__ void prefix_kernel(const int* __restrict__ cnt, int* __restrict__ base) {
    if (threadIdx.x == 0) {
        int s = 0;
#pragma unroll
        for (int e = 0; e < NEXP; e++) { base[e] = s; s += cnt[e]; }
    }
}
__global__ void __launch_bounds__(256)
combine_kernel(const float* __restrict__ ys, const int* __restrict__ base,
               const int2* __restrict__ tokE, const int2* __restrict__ tokP,
               const float2* __restrict__ tokW, uint16_t* __restrict__ m16)
{
    const int t = blockIdx.x;
    int2 te = tokE[t];
    int2 tp = tokP[t];
    float2 tw = tokW[t];
    long long s0 = (long long)(base[te.x] + tp.x) * DDIM;
    long long s1 = (long long)(base[te.y] + tp.y) * DDIM;
    int c = threadIdx.x * 4;
    float4 y0 = *reinterpret_cast<const float4*>(ys + s0 + c);
    float4 y1 = *reinterpret_cast<const float4*>(ys + s1 + c);
    float4 v;
    v.x = tw.x * y0.x + tw.y * y1.x;
    v.y = tw.x * y0.y + tw.y * y1.y;
    v.z = tw.x * y0.z + tw.y * y1.z;
    v.w = tw.x * y0.w + tw.y * y1.w;
    __half2 a = __floats2half2_rn(v.x, v.y);
    __half2 b = __floats2half2_rn(v.z, v.w);
    long long idx = ((long long)t * DDIM + c) >> 2;
    reinterpret_cast<uint2*>(m16)[idx] =
        make_uint2(*reinterpret_cast<uint32_t*>(&a),
                   *reinterpret_cast<uint32_t*>(&b));
}

// ---------------- unified tensor-core GEMM ----------------
// MODE 0: 3-term bf16 split, CHUNK_K=32. MODE 1: single fp16, CHUNK_K=64.
template<int MODE>
__global__ void __launch_bounds__(512, 1)
tc_gemm(const uint16_t* __restrict__ Ah_g, const uint16_t* __restrict__ Al_g,
        const uint16_t* __restrict__ Bh_g, const uint16_t* __restrict__ Bl_g,
        size_t bStride,
        float* __restrict__ Cf, uint16_t* __restrict__ Oh,
        const float* __restrict__ bias,
        const int* __restrict__ gatherIdx,
        const int* __restrict__ cntPtr, const int* __restrict__ basePtr,
        int Mfix, int N, int K, int doRelu)
{
    extern __shared__ char smem[];

    constexpr int CK          = (MODE == 0) ? 32 : 64;   // k per chunk
    constexpr int KSTEPS      = CK / 16;
    constexpr uint32_t ARB    = CK * 2;                  // A row bytes
    constexpr uint32_t AMASK  = ARB / 16 - 1;            // swizzle mask
    constexpr uint32_t APL    = 256 * ARB;               // A plane bytes
    constexpr uint32_t BOFF   = 32768;                   // both modes: A region 32KB
    constexpr uint32_t BPL    = CK * 256;                // B plane bytes
    constexpr uint32_t BUFB   = 49152;                   // 48KB per buffer
    constexpr int AUPT        = (MODE == 0) ? 2 : 4;     // A 16B-units per thread
    constexpr int BUPT        = (MODE == 0) ? 1 : 2;     // B 16B-units per thread

    const int z = blockIdx.z;
    int M = cntPtr ? __ldg(cntPtr + z) : Mfix;
    const int obase = basePtr ? __ldg(basePtr + z) : 0;
    const int row0 = blockIdx.y * 256;
    if (row0 >= M) return;
    const int col0 = blockIdx.x * 128;

    const int tid  = threadIdx.x;
    const int lane = tid & 31;
    const int wid  = tid >> 5;
    const int wm   = wid >> 2;
    const int wn   = wid & 3;

    const uint32_t smem_base = smem_u32(smem);

    const uint16_t* Bh_e = Bh_g + (size_t)z * bStride;
    const uint16_t* Bl_e = (MODE == 0) ? Bl_g + (size_t)z * bStride : nullptr;
    const float* bias_e = bias ? bias + (size_t)z * N : nullptr;
    const int* gIdx = gatherIdx ? gatherIdx + (size_t)z * NTOK : nullptr;

    // producer mapping
    const int rA  = tid >> 1;
    const int uA0 = (tid & 1) * AUPT;
    const int kB  = tid / (512 / CK);
    const int uB0 = (tid & (512 / CK - 1)) * BUPT;

    const int mA = row0 + rA;
    const int aOk = (mA < M) ? 16 : 0;
    const int gA = (mA < M) ? (gIdx ? gIdx[mA] : obase + mA) : 0;
    const uint16_t* aSrcH = Ah_g + (long long)gA * K;
    const uint16_t* aSrcL = (MODE == 0) ? Al_g + (long long)gA * K : nullptr;

    const int nchunk = K / CK;

    auto prefetch = [&](int c) {
        int b = c % NBUF;
        int k0 = c * CK;
        uint32_t base = smem_base + b * BUFB;
#pragma unroll
        for (int p = 0; p < AUPT; p++) {
            int u = uA0 + p;
            uint32_t d = base + rA * ARB + ((u ^ (rA & AMASK)) << 4);
            cp_async16(d, aSrcH + k0 + u * 8, aOk);
            if constexpr (MODE == 0)
                cp_async16(d + APL, aSrcL + k0 + u * 8, aOk);
        }
#pragma unroll
        for (int p = 0; p < BUPT; p++) {
            int u = uB0 + p;
            uint32_t d = base + BOFF + kB * 256 + ((u ^ (kB & 7)) << 4);
            long long go = (long long)(k0 + kB) * N + col0 + u * 8;
            cp_async16(d, Bh_e + go, 16);
            if constexpr (MODE == 0)
                cp_async16(d + BPL, Bl_e + go, 16);
        }
        CP_COMMIT();
    };

    const int rowA  = wm * 64 + (lane & 7) + ((lane >> 3) & 1) * 8;
    const int kbA   = (lane >> 4) & 1;
    const int swzA  = rowA & AMASK;
    const int kBld  = (lane & 7) + ((lane >> 3) & 1) * 8;
    const int nbB   = (lane >> 4) & 1;
    const int kswzB = kBld & 7;

    float acc[4][4][4];
#pragma unroll
    for (int mi = 0; mi < 4; mi++)
#pragma unroll
        for (int nj = 0; nj < 4; nj++)
#pragma unroll
            for (int q = 0; q < 4; q++) acc[mi][nj][q] = 0.f;

    prefetch(0);
    prefetch(1);

    for (int c = 0; c < nchunk; c++) {
        if (c + 1 < nchunk) { CP_WAIT(1); } else { CP_WAIT(0); }
        __syncthreads();
        if (c + 2 < nchunk) prefetch(c + 2);

        const int b = c % NBUF;
        const uint32_t bufAh = smem_base + b * BUFB;
        const uint32_t bufAl = bufAh + APL;
        const uint32_t bufBh = bufAh + BOFF;
        const uint32_t bufBl = bufBh + BPL;

#pragma unroll
        for (int ks = 0; ks < KSTEPS; ks++) {
            uint32_t bh[2][4], bl[2][4];
#pragma unroll
            for (int j = 0; j < 2; j++) {
                int nchk = wn * 4 + j * 2 + nbB;
                uint32_t boff = (uint32_t)((kBld + ks * 16) * 256 +
                                ((nchk ^ kswzB) << 4));
                ldsm_x4_t(bh[j], bufBh + boff);
                if constexpr (MODE == 0) ldsm_x4_t(bl[j], bufBl + boff);
            }
#pragma unroll
            for (int mi = 0; mi < 4; mi++) {
                uint32_t ah[4], al[4];
                uint32_t aoff = (uint32_t)((rowA + mi * 16) * ARB +
                                (((ks * 2 + kbA) ^ swzA) << 4));
                ldsm_x4(ah, bufAh + aoff);
                if constexpr (MODE == 0) ldsm_x4(al, bufAl + aoff);
#pragma unroll
                for (int nj = 0; nj < 4; nj++) {
                    int j = nj >> 1, p = (nj & 1) * 2;
                    uint32_t b0h = bh[j][p], b1h = bh[j][p + 1];
                    if constexpr (MODE == 0) {
                        uint32_t b0l = bl[j][p], b1l = bl[j][p + 1];
                        mma_bf16(acc[mi][nj], ah[0], ah[1], ah[2], ah[3], b0h, b1h);
                        mma_bf16(acc[mi][nj], ah[0], ah[1], ah[2], ah[3], b0l, b1l);
                        mma_bf16(acc[mi][nj], al[0], al[1], al[2], al[3], b0h, b1h);
                    } else {
                        mma_f16(acc[mi][nj], ah[0], ah[1], ah[2], ah[3], b0h, b1h);
                    }
                }
            }
        }
    }

    // ---------------- epilogue ----------------
    const int colBase = col0 + wn * 32 + (lane & 3) * 2;
#pragma unroll
    for (int mi = 0; mi < 4; mi++) {
        int r0 = row0 + wm * 64 + mi * 16 + (lane >> 2);
        int r1 = r0 + 8;
#pragma unroll
        for (int nj = 0; nj < 4; nj++) {
            int col = colBase + nj * 8;
            float b0 = bias_e ? bias_e[col] : 0.f;
            float b1 = bias_e ? bias_e[col + 1] : 0.f;
            float v00 = acc[mi][nj][0] + b0;
            float v01 = acc[mi][nj][1] + b1;
            float v10 = acc[mi][nj][2] + b0;
            float v11 = acc[mi][nj][3] + b1;
            if (doRelu) {
                v00 = fmaxf(v00, 0.f); v01 = fmaxf(v01, 0.f);
                v10 = fmaxf(v10, 0.f); v11 = fmaxf(v11, 0.f);
            }
            if (r0 < M) {
                long long o = (long long)(obase + r0) * N + col;
                if (Cf) { Cf[o] = v00; Cf[o + 1] = v01; }
                if (Oh) {
                    __half2 hv = __floats2half2_rn(v00, v01);
                    *reinterpret_cast<uint32_t*>(Oh + o) =
                        *reinterpret_cast<uint32_t*>(&hv);
                }
            }
            if (r1 < M) {
                long long o = (long long)(obase + r1) * N + col;
                if (Cf) { Cf[o] = v10; Cf[o + 1] = v11; }
                if (Oh) {
                    __half2 hv = __floats2half2_rn(v10, v11);
                    *reinterpret_cast<uint32_t*>(Oh + o) =
                        *reinterpret_cast<uint32_t*>(&hv);
                }
            }
        }
    }
}

// ---------------- gating ----------------
__global__ void __launch_bounds__(256)
gate_kernel(const float* __restrict__ h, const float* __restrict__ Wg,
            int* __restrict__ cnt, int* __restrict__ bidx,
            int2* __restrict__ tokE, int2* __restrict__ tokP,
            float2* __restrict__ tokW)
{
    __shared__ float sWg[DDIM * NEXP];
    const int tid = threadIdx.x;
    for (int i = tid; i < DDIM * NEXP; i += 256) sWg[i] = Wg[i];
    __syncthreads();

    const int warp = tid >> 5;
    const int lane = tid & 31;
    const int token = blockIdx.x * 8 + warp;
    if (token >= NTOK) return;

    float accv[NEXP];
#pragma unroll
    for (int e = 0; e < NEXP; e++) accv[e] = 0.f;
    const float* hrow = h + (long long)token * DDIM;
    for (int d = lane; d < DDIM; d += 32) {
        float hv = hrow[d];
#pragma unroll
        for (int e = 0; e < NEXP; e++)
            accv[e] = fmaf(hv, sWg[d * NEXP + e], accv[e]);
    }
#pragma unroll
    for (int e = 0; e < NEXP; e++) {
#pragma unroll
        for (int off = 16; off > 0; off >>= 1)
            accv[e] += __shfl_xor_sync(0xffffffffu, accv[e], off);
    }
    if (lane == 0) {
        int i1 = 0; float l1 = accv[0];
#pragma unroll
        for (int e = 1; e < NEXP; e++)
            if (accv[e] > l1) { l1 = accv[e]; i1 = e; }
        int i2 = -1; float l2 = -3.0e38f;
#pragma unroll
        for (int e = 0; e < NEXP; e++)
            if (e != i1 && accv[e] > l2) { l2 = accv[e]; i2 = e; }
        float p2 = expf(l2 - l1);
        float w1 = 1.f / (1.f + p2);
        float w2 = p2 * w1;
        int p = atomicAdd(&cnt[i1], 1);
        bidx[i1 * NTOK + p] = token;
        int q = atomicAdd(&cnt[i2], 1);
        bidx[i2 * NTOK + q] = token;
        tokE[token] = make_int2(i1, i2);
        tokP[token] = make_int2(p, q);
        tokW[token] = make_float2(w1, w2);
    }
}

// ---------------- launch ----------------
extern "C" void kernel_launch(void* const* d_in, const int* in_sizes, int n_in,
                              void* d_out, int out_size)
{
    const float* x      = (const float*)d_in[0];
    const float* W_in   = (const float*)d_in[1];
    const float* b_in   = (const float*)d_in[2];
    const float* W_gate = (const float*)d_in[3];
    const float* W1     = (const float*)d_in[4];
    const float* b1     = (const float*)d_in[5];
    const float* W2     = (const float*)d_in[6];
    const float* b2     = (const float*)d_in[7];
    const float* W_head = (const float*)d_in[8];
    float* out = (float*)d_out;

    float *h_p, *ys_p;
    int *cnt_p, *base_p, *bidx_p;
    int2 *tokE_p, *tokP_p;
    float2 *tokW_p;
    uint16_t *xh, *xl, *wih, *wil, *h16, *he16, *m16, *w1f, *w2f, *whf;
    cudaGetSymbolAddress((void**)&h_p,   g_h);
    cudaGetSymbolAddress((void**)&ys_p,  g_ys);
    cudaGetSymbolAddress((void**)&cnt_p, g_cnt);
    cudaGetSymbolAddress((void**)&base_p,g_base);
    cudaGetSymbolAddress((void**)&bidx_p,g_bidx);
    cudaGetSymbolAddress((void**)&tokE_p,g_tokE);
    cudaGetSymbolAddress((void**)&tokP_p,g_tokP);
    cudaGetSymbolAddress((void**)&tokW_p,g_tokW);
    cudaGetSymbolAddress((void**)&xh,  g_xh);  cudaGetSymbolAddress((void**)&xl,  g_xl);
    cudaGetSymbolAddress((void**)&wih, g_wih); cudaGetSymbolAddress((void**)&wil, g_wil);
    cudaGetSymbolAddress((void**)&h16, g_h16);
    cudaGetSymbolAddress((void**)&he16,g_he16);
    cudaGetSymbolAddress((void**)&m16, g_m16);
    cudaGetSymbolAddress((void**)&w1f, g_w1f);
    cudaGetSymbolAddress((void**)&w2f, g_w2f);
    cudaGetSymbolAddress((void**)&whf, g_whf);

    cudaFuncSetAttribute(tc_gemm<0>,
                         cudaFuncAttributeMaxDynamicSharedMemorySize, NBUF * 49152);
    cudaFuncSetAttribute(tc_gemm<1>,
                         cudaFuncAttributeMaxDynamicSharedMemorySize, NBUF * 49152);

    zero_i_kernel<<<1, 32>>>(cnt_p, NEXP);
    split_kernel<<<2048, 256>>>(x,    xh,  xl,  (long long)NTOK * DDIM / 4);
    split_kernel<<<512,  256>>>(W_in, wih, wil, (long long)DDIM * DDIM / 4);
    tohalf_kernel<<<4096, 256>>>(W1,     w1f, (long long)NEXP * DDIM * HDIM / 4);
    tohalf_kernel<<<1024, 256>>>(W_head, whf, (long long)DDIM * DOUT / 4);

    // h = x @ W_in + b_in  -> fp32 (gate) + fp16 (up input), 3-term bf16 split
    tc_gemm<0><<<dim3(DDIM / 128, NTOK / 256, 1), 512, NBUF * 49152>>>(
        xh, xl, wih, wil, 0,
        h_p, h16, b_in,
        nullptr, nullptr, nullptr, NTOK, DDIM, DDIM, 0);

    gate_kernel<<<NTOK / 8, 256>>>(h_p, W_gate, cnt_p, bidx_p, tokE_p, tokP_p, tokW_p);
    prefix_kernel<<<1, 32>>>(cnt_p, base_p);
    tohalf_kernel<<<4096, 256>>>(W2, w2f, (long long)NEXP * HDIM * DDIM / 4);

    // up: he[base[e]+m] = relu(h16[bidx[e,m]] @ W1f[e] + b1[e]) -> fp16
    tc_gemm<1><<<dim3(HDIM / 128, NTOK / 256, NEXP), 512, NBUF * 49152>>>(
        h16, nullptr, w1f, nullptr, (size_t)DDIM * HDIM,
        nullptr, he16, b1,
        bidx_p, cnt_p, base_p, 0, HDIM, DDIM, 1);

    // down: ys[base[e]+m] = he16 @ W2f[e] + b2[e]
    tc_gemm<1><<<dim3(DDIM / 128, NTOK / 256, NEXP), 512, NBUF * 49152>>>(
        he16, nullptr, w2f, nullptr, (size_t)HDIM * DDIM,
        ys_p, nullptr, b2,
        nullptr, cnt_p, base_p, 0, DDIM, HDIM, 0);

    // combine -> fp16 plane for head
    combine_kernel<<<NTOK, 256>>>(ys_p, base_p, tokE_p, tokP_p, tokW_p, m16);

    // head: out = m16 @ Whf
    tc_gemm<1><<<dim3(DOUT / 128, NTOK / 256, 1), 512, NBUF * 49152>>>(
        m16, nullptr, whf, nullptr, 0,
        out, nullptr, nullptr,
        nullptr, nullptr, nullptr, NTOK, DOUT, DDIM, 0);
}